// round 11
// baseline (speedup 1.0000x reference)
#include <cuda_runtime.h>
#include <math.h>
#include <cstring>

// MatchedFilterLoss fused kernel for GB300 (sm_103a)
// Single kernel: 512 blocks x 256 threads. Pearson computed spectrally.
// FFT#1: 2048-pt radix-8 (stage-1 from registers, register twiddles).
// FFT#2: Hermitian->real via half-size 1024-pt complex FFT (radix-4 x5).
// Shared addresses: zs(base) ^ compile-time XOR constants.
// Complex add/sub: packed f32x2 PTX ops (one instruction per complex op).

#define NTH 256
#define FULLM 0xffffffffu

// storage position of natural frequency k after radix-[8,8,8,4] DIF (2048)
__device__ __forceinline__ int fpos8(int k)
{
    return ((k & 7) << 8) | (((k >> 3) & 7) << 5) | (((k >> 6) & 7) << 2) | (k >> 9);
}

// storage position of frequency m after radix-[4,4,4,4,4] DIF (1024)
__device__ __forceinline__ int rev4(int m)
{
    return ((m & 3) << 8) | (((m >> 2) & 3) << 6) | (((m >> 4) & 3) << 4)
         | (((m >> 6) & 3) << 2) | (m >> 8);
}

// bank swizzle for float2 array z (XOR-linear)
__device__ __forceinline__ int zs(int p)
{
    return p ^ ((p >> 4) & 15) ^ ((p >> 8) & 7) ^ (((p >> 6) & 1) << 3);
}
// constexpr version for compile-time offset constants
__device__ constexpr int zc(int m)
{
    return m ^ ((m >> 4) & 15) ^ ((m >> 8) & 7) ^ (((m >> 6) & 1) << 3);
}

// ---- packed f32x2 complex add/sub (single instruction each) -------------
__device__ __forceinline__ unsigned long long f2u(float2 a)
{
    unsigned long long u; memcpy(&u, &a, 8); return u;
}
__device__ __forceinline__ float2 u2f(unsigned long long u)
{
    float2 a; memcpy(&a, &u, 8); return a;
}
__device__ __forceinline__ float2 c_add(float2 a, float2 b)
{
    unsigned long long r;
    asm("add.rn.f32x2 %0, %1, %2;" : "=l"(r) : "l"(f2u(a)), "l"(f2u(b)));
    return u2f(r);
}
__device__ __forceinline__ float2 c_sub(float2 a, float2 b)
{
    unsigned long long r;
    asm("sub.rn.f32x2 %0, %1, %2;" : "=l"(r) : "l"(f2u(a)), "l"(f2u(b)));
    return u2f(r);
}

__device__ __forceinline__ float2 cmul2(float2 a, float2 w)
{
    return make_float2(a.x*w.x - a.y*w.y, a.x*w.y + a.y*w.x);
}

// w_2048^e = exp(-i*pi*e/1024)
__device__ __forceinline__ float2 tw2048(int e)
{
    float2 w;
    sincospif(-(float)e * (1.0f / 1024.0f), &w.y, &w.x);
    return w;
}

// radix-8 DIF butterfly
__device__ __forceinline__ void radix8_core(float2* x)
{
    const float H = 0.70710678118654752f;
    float2 a0=c_add(x[0],x[4]), d0=c_sub(x[0],x[4]);
    float2 a1=c_add(x[1],x[5]), d1=c_sub(x[1],x[5]);
    float2 a2=c_add(x[2],x[6]), d2=c_sub(x[2],x[6]);
    float2 a3=c_add(x[3],x[7]), d3=c_sub(x[3],x[7]);
    float2 b0=d0;
    float2 b1=make_float2(H*(d1.x+d1.y), H*(d1.y-d1.x));
    float2 b2=make_float2(d2.y, -d2.x);
    float2 b3=make_float2(H*(d3.y-d3.x), -H*(d3.x+d3.y));
    float2 t0=c_add(a0,a2), t1=c_add(a1,a3), t2=c_sub(a0,a2);
    float2 u =c_sub(a1,a3); float2 t3=make_float2(u.y,-u.x);
    x[0]=c_add(t0,t1); x[2]=c_add(t2,t3); x[4]=c_sub(t0,t1); x[6]=c_sub(t2,t3);
    t0=c_add(b0,b2); t1=c_add(b1,b3); t2=c_sub(b0,b2);
    u=c_sub(b1,b3); t3=make_float2(u.y,-u.x);
    x[1]=c_add(t0,t1); x[3]=c_add(t2,t3); x[5]=c_sub(t0,t1); x[7]=c_sub(t2,t3);
}

// store radix-8 outputs at precomputed addresses; twiddles chained from w1
__device__ __forceinline__ void bfly8_store_ad(float2* z, const float2* x, const int* ad, float2 w1)
{
    float2 w2 = cmul2(w1, w1);
    float2 w3 = cmul2(w2, w1);
    float2 w4 = cmul2(w2, w2);
    float2 w5 = cmul2(w2, w3);
    float2 w6 = cmul2(w3, w3);
    float2 w7 = cmul2(w3, w4);
    z[ad[0]] = x[0];
    z[ad[1]] = cmul2(x[1], w1);
    z[ad[2]] = cmul2(x[2], w2);
    z[ad[3]] = cmul2(x[3], w3);
    z[ad[4]] = cmul2(x[4], w4);
    z[ad[5]] = cmul2(x[5], w5);
    z[ad[6]] = cmul2(x[6], w6);
    z[ad[7]] = cmul2(x[7], w7);
}

template<int Q>
__device__ __forceinline__ void stage8_z(float2* z, int tid, float2 w1)
{
    const int j    = tid & (Q - 1);
    const int base = (tid / Q) * (Q * 8) + j;
    const int pb   = zs(base);
    int ad[8];
#pragma unroll
    for (int s = 0; s < 8; s++) ad[s] = pb ^ zc(Q * s);
    float2 x[8];
#pragma unroll
    for (int s = 0; s < 8; s++) x[s] = z[ad[s]];
    radix8_core(x);
    bfly8_store_ad(z, x, ad, w1);
}

// radix-4 DIF butterfly (in place)
__device__ __forceinline__ void radix4_core(float2* x)
{
    float2 t0=c_add(x[0],x[2]), t1=c_add(x[1],x[3]), t2=c_sub(x[0],x[2]);
    float2 u =c_sub(x[1],x[3]); float2 t3=make_float2(u.y,-u.x);
    x[0]=c_add(t0,t1); x[1]=c_add(t2,t3); x[2]=c_sub(t0,t1); x[3]=c_sub(t2,t3);
}

__device__ __forceinline__ void bfly4_store_ad(float2* z, const float2* x, const int* ad, float2 w1)
{
    float2 w2 = cmul2(w1, w1), w3 = cmul2(w2, w1);
    z[ad[0]] = x[0];
    z[ad[1]] = cmul2(x[1], w1);
    z[ad[2]] = cmul2(x[2], w2);
    z[ad[3]] = cmul2(x[3], w3);
}

__global__ __launch_bounds__(256, 4)
void mfl_kernel(const float* __restrict__ xhat_g,
                const float* __restrict__ x_g,
                float* __restrict__ out)
{
    __shared__ __align__(16) float xh[2048];   // centered x_hat
    __shared__ __align__(16) float yc[2048];   // raw x
    __shared__ __align__(16) float xv[2048];   // integrands a|cm, then cumsums
    __shared__ float2 z[2048];                 // FFT workspace (bank-swizzled)
    __shared__ float P1[52], P2[52], Q1[52], Q2[52];
    __shared__ float red1[24], red2[24];
    __shared__ float wA[8], wB[8];
    __shared__ float wmax[7];
    __shared__ float s_total, s_tot2raw, s_inv;
    __shared__ int   s_edges[17];

    const int tid  = threadIdx.x;
    const int lane = tid & 31;
    const int wid  = tid >> 5;
    const int row  = blockIdx.x;

    const float* xh_in = xhat_g + (size_t)row * 2048;
    const float* x_in  = x_g    + (size_t)row * 2048;

    // per-thread twiddles, computed once
    float2 twA = tw2048(tid);               // 2048 FFT Q=256 stage + twist base
    float2 twB = tw2048(8 * (tid & 31));    // 2048 FFT Q=32
    float2 twC = tw2048(64 * (tid & 3));    // 2048 FFT Q=4
    float2 twE = tw2048(8 * (tid & 63));    // 1024 FFT stage1 (Q=64)
    float2 twF = tw2048(32 * (tid & 15));   // 1024 FFT stage2 (Q=16)
    float2 twG = tw2048(128 * (tid >> 6));  // 1024 FFT stage3 (Q=4, j=tid>>6)

    // ---- 1. register-resident load + min/max/mean ------------------------
    float hr[8], xr[8];
#pragma unroll
    for (int s = 0; s < 8; s++) {
        hr[s] = xh_in[tid + 256 * s];
        xr[s] = x_in[tid + 256 * s];
    }
    float mn, mx, my;
    {
        float pmn = 1e30f, pmx = -1e30f, psy = 0.f;
#pragma unroll
        for (int s = 0; s < 8; s++) {
            pmn = fminf(pmn, hr[s]); pmx = fmaxf(pmx, hr[s]); psy += xr[s];
        }
        for (int o = 16; o; o >>= 1) {
            pmn = fminf(pmn, __shfl_xor_sync(FULLM, pmn, o));
            pmx = fmaxf(pmx, __shfl_xor_sync(FULLM, pmx, o));
            psy += __shfl_xor_sync(FULLM, psy, o);
        }
        if (lane == 0) { red1[wid] = pmn; red1[8 + wid] = pmx; red1[16 + wid] = psy; }
        __syncthreads();
        mn = red1[0]; mx = red1[8]; my = red1[16];
#pragma unroll
        for (int w = 1; w < 8; w++) {
            mn = fminf(mn, red1[w]);
            mx = fmaxf(mx, red1[8 + w]);
            my += red1[16 + w];
        }
        my *= (1.0f / 2048.0f);
    }

    // ---- 2. center in regs, write xh/yc, totals --------------------------
    {
        float inv = 1.0f / (mx - mn);
        float t1 = 0.f, t2 = 0.f, vy = 0.f;
#pragma unroll
        for (int s = 0; s < 8; s++) {
            float h = 2.0f * (hr[s] - mn) * inv - 1.0f;
            hr[s] = h;
            xh[tid + 256 * s] = h;
            yc[tid + 256 * s] = xr[s];
            float y = xr[s] - my;
            t1 += h; t2 += h * h; vy += y * y;
        }
        for (int o = 16; o; o >>= 1) {
            t1 += __shfl_xor_sync(FULLM, t1, o);
            t2 += __shfl_xor_sync(FULLM, t2, o);
            vy += __shfl_xor_sync(FULLM, vy, o);
        }
        if (lane == 0) { red2[wid] = t1; red2[8 + wid] = t2; red2[16 + wid] = vy; }
        __syncthreads();
    }

    // ---- 3. FFT#1 stage 1 from registers; P/Q prefix scans ---------------
    {
        float2 x[8];
#pragma unroll
        for (int s = 0; s < 8; s++) x[s] = make_float2(hr[s], xr[s]);
        radix8_core(x);
        {
            const int pb = zs(tid);
            int ad[8];
#pragma unroll
            for (int s = 0; s < 8; s++) ad[s] = pb ^ zc(256 * s);
            bfly8_store_ad(z, x, ad, twA);
        }

        // P (head) and Q (tail) prefix sums as warp scans
        if (wid == 0) {
            float a0 = 0.f, a1 = 0.f;
            if (lane < 26) { float2 v = ((const float2*)xh)[lane]; a0 = v.x; a1 = v.y; }
            float s1 = a0 + a1, s2 = a0 * a0 + a1 * a1;
            float i1 = s1, i2 = s2;
            for (int o = 1; o < 32; o <<= 1) {
                float u1 = __shfl_up_sync(FULLM, i1, o);
                float u2 = __shfl_up_sync(FULLM, i2, o);
                if (lane >= o) { i1 += u1; i2 += u2; }
            }
            if (lane < 26) {
                float e1 = i1 - s1, e2 = i2 - s2;
                P1[2*lane] = e1;  P1[2*lane+1] = e1 + a0;
                P2[2*lane] = e2;  P2[2*lane+1] = e2 + a0 * a0;
            }
        } else if (wid == 1) {
            float b0 = 0.f, b1 = 0.f;
            if (lane < 26) {
                float2 v = ((const float2*)xh)[1023 - lane];  // {xh[2046-2l], xh[2047-2l]}
                b0 = v.y; b1 = v.x;
            }
            float s1 = b0 + b1, s2 = b0 * b0 + b1 * b1;
            float i1 = s1, i2 = s2;
            for (int o = 1; o < 32; o <<= 1) {
                float u1 = __shfl_up_sync(FULLM, i1, o);
                float u2 = __shfl_up_sync(FULLM, i2, o);
                if (lane >= o) { i1 += u1; i2 += u2; }
            }
            if (lane < 26) {
                float e1 = i1 - s1, e2 = i2 - s2;
                Q1[2*lane] = e1;  Q1[2*lane+1] = e1 + b0;
                Q2[2*lane] = e2;  Q2[2*lane+1] = e2 + b0 * b0;
            }
        }
        __syncthreads();
    }
    stage8_z<32>(z, tid, twB); __syncthreads();
    stage8_z<4>(z, tid, twC);  __syncthreads();
    // final radix-4 of FFT#1
#pragma unroll
    for (int it = 0; it < 2; it++) {
        int pb = zs(4 * (tid + it * 256));
        float2 x[4];
#pragma unroll
        for (int r = 0; r < 4; r++) x[r] = z[pb ^ r];
        radix4_core(x);
#pragma unroll
        for (int r = 0; r < 4; r++) z[pb ^ r] = x[r];
    }
    __syncthreads();

    // ---- 4. untangle: chisq integrands; write P[k] into z[0..1024] -------
    {
        const int zsC[4] = { 0, 17, 1, 16 };   // zs0(fpos8(256*it))
        const int zsW[4] = { 18, 3, 19, 2 };   // zs0(fpos8(256*(7-it)))
        const int azS[4] = { 17, 1, 16, 2 };   // tid==255: zs(fpos8(256*(1+it)))
        const int pz = zs(fpos8(1 + tid));
        const int pw = zs(fpos8(255 - tid));
        const int pk = zs(1 + tid);
        float2 Pk[4];
#pragma unroll
        for (int it = 0; it < 4; it++) {
            int k  = 1 + tid + it * 256;         // 1..1024
            int aZ = (tid == 255) ? azS[it] : (pz ^ zsC[it]);
            int aW = pw ^ zsW[it];
            float2 Z = z[aZ];
            float2 W = z[aW];
            const float sc = 0.5f / 2048.0f;
            float h_r = (Z.x + W.x) * sc, h_i = (Z.y - W.y) * sc;
            float s_r = (Z.y + W.y) * sc, s_i = (W.x - Z.x) * sc;
            float pr = h_r * s_r + h_i * s_i;
            float pi = h_i * s_r - h_r * s_i;
            if (k >= 32) {
                float a  = 4.0f * (h_r * h_r + h_i * h_i);
                float cm = 4.0f * sqrtf(pr * pr + pi * pi);
                xv[k - 32]        = a;
                xv[1024 + k - 32] = cm;
            }
            Pk[it] = make_float2(pr, pi);
        }
        __syncthreads();                         // all reads of FFT#1 output done
#pragma unroll
        for (int it = 0; it < 4; it++) {
            int aP = (tid == 255) ? (257 * (1 + it)) : (pk ^ (257 * it));
            z[aP] = Pk[it];
        }
        if (tid == 0) z[0] = make_float2(0.f, 0.f);   // zs(0)=0: P[0] := 0
        __syncthreads();
    }

    // ---- 5. FFT#2: Hermitian->real via 1024-pt complex FFT ---------------
    {
        const float Hc = 0.70710678118654752f;
        float2 V[4];
        {
            const int pa  = zs(tid);
            const int pb2 = (tid == 0) ? 0 : zs(256 - tid);
            float2 a[4], b[4];
#pragma unroll
            for (int s = 0; s < 4; s++) {
                a[s] = z[pa ^ (257 * s)];
                b[s] = (tid == 0) ? z[257 * (4 - s)] : z[pb2 ^ (257 * (3 - s))];
            }
#pragma unroll
            for (int s = 0; s < 4; s++) {
                float2 w8s = (s == 0) ? make_float2(1.f, 0.f)
                           : (s == 1) ? make_float2(Hc, -Hc)
                           : (s == 2) ? make_float2(0.f, -1.f)
                                      : make_float2(-Hc, -Hc);
                float2 ca  = make_float2(a[s].x, -a[s].y);
                float2 sum = c_add(ca, b[s]);
                float2 dif = c_sub(ca, b[s]);
                float2 twk = cmul2(twA, w8s);         // e^{-i pi k/1024}
                float2 idt = cmul2(dif, twk);
                V[s] = make_float2(sum.x - idt.y, sum.y + idt.x);
            }
            __syncthreads();                      // all P reads done before overwrite
            radix4_core(V);
            float2 w1 = cmul2(twA, twA);          // w_1024^tid
            int ad[4];
#pragma unroll
            for (int r = 0; r < 4; r++) ad[r] = pa ^ zc(256 * r);
            bfly4_store_ad(z, V, ad, w1);
            __syncthreads();
        }
        // stage 1: Q=64
        {
            int base = (tid >> 6) * 256 + (tid & 63);
            int pb = zs(base);
            int ad[4];
#pragma unroll
            for (int r = 0; r < 4; r++) ad[r] = pb ^ zc(64 * r);
            float2 x[4];
#pragma unroll
            for (int r = 0; r < 4; r++) x[r] = z[ad[r]];
            radix4_core(x);
            bfly4_store_ad(z, x, ad, twE);
            __syncthreads();
        }
        // stage 2: Q=16
        {
            int base = (tid >> 4) * 64 + (tid & 15);
            int pb = zs(base);
            int ad[4];
#pragma unroll
            for (int r = 0; r < 4; r++) ad[r] = pb ^ zc(16 * r);
            float2 x[4];
#pragma unroll
            for (int r = 0; r < 4; r++) x[r] = z[ad[r]];
            radix4_core(x);
            bfly4_store_ad(z, x, ad, twF);
            __syncthreads();
        }
        // stage 3: Q=4 (j = tid>>6 remap keeps banks conflict-free)
        {
            int base = (tid & 63) * 16 + (tid >> 6);
            int pb = zs(base);
            int ad[4];
#pragma unroll
            for (int r = 0; r < 4; r++) ad[r] = pb ^ zc(4 * r);
            float2 x[4];
#pragma unroll
            for (int r = 0; r < 4; r++) x[r] = z[ad[r]];
            radix4_core(x);
            bfly4_store_ad(z, x, ad, twG);
            __syncthreads();
        }
        // stage 4 (final, untwiddled) pruned to quads feeding needed outputs
        {
            int b = tid;
            int m0 = ((b & 3) << 6) | (((b >> 2) & 3) << 4) | (((b >> 4) & 3) << 2) | (b >> 6);
            if (m0 <= 25 || m0 >= 230) {
                int pb = zs(4 * b);
                float2 x[4];
#pragma unroll
                for (int r = 0; r < 4; r++) x[r] = z[pb ^ r];
                radix4_core(x);
#pragma unroll
                for (int r = 0; r < 4; r++) z[pb ^ r] = x[r];
            }
            __syncthreads();
        }
    }

    // ---- 6. circular->linear corrections, Pearson corr, max -------------
    if (tid < 224) {                      // warps 0..6, 2 threads per shift
        const int pid = tid >> 1;
        const int h   = tid & 1;
        const bool act = (pid < 103);
        float wrap = 0.f, rc = 0.f;
        int d = 0;
        if (act) {
            d = pid - 51;
            int dc = d & 2047;
            int m  = dc >> 1;
            float2 val = z[zs(rev4(m))];
            rc = 2048.0f * ((dc & 1) ? val.y : val.x);
            if (d > 0) {
                for (int t = h; t < d; t += 2) wrap += xh[t] * (yc[2048 - d + t] - my);
            } else if (d < 0) {
                int mm = -d;
                for (int t = h; t < mm; t += 2) wrap += xh[2048 - mm + t] * (yc[t] - my);
            }
        }
        wrap += __shfl_xor_sync(FULLM, wrap, 1);
        float corr = -2.f;
        if (act) {
            float T1 = red2[0], T2 = red2[8], Vy = red2[16];
#pragma unroll
            for (int w = 1; w < 8; w++) {
                T1 += red2[w]; T2 += red2[8 + w]; Vy += red2[16 + w];
            }
            float acc = rc - wrap;
            float S1, S2v;
            if (d >= 0) { S1 = T1 - P1[d];  S2v = T2 - P2[d]; }
            else        { S1 = T1 - Q1[-d]; S2v = T2 - Q2[-d]; }
            float varx = S2v - S1 * S1 * (1.0f / 2048.0f);
            corr = acc / sqrtf(varx * Vy);
        }
        for (int o = 16; o; o >>= 1)
            corr = fmaxf(corr, __shfl_xor_sync(FULLM, corr, o));
        if (lane == 0) wmax[wid] = corr;
    }
    __syncthreads();

    // ---- 7. dual parallel inclusive scan over 993 elements --------------
    {
        const int i0 = tid * 4;
        float4 a4 = ((const float4*)xv)[tid];
        float4 b4 = ((const float4*)xv)[256 + tid];
        float av[4] = { a4.x, a4.y, a4.z, a4.w };
        float bv[4] = { b4.x, b4.y, b4.z, b4.w };
#pragma unroll
        for (int u = 0; u < 4; u++) {
            if (i0 + u >= 993) { av[u] = 0.f; bv[u] = 0.f; }
        }
        av[1] += av[0]; av[2] += av[1]; av[3] += av[2];
        bv[1] += bv[0]; bv[2] += bv[1]; bv[3] += bv[2];
        float la = av[3], lb = bv[3];
        float ainc = la, binc = lb;
#pragma unroll
        for (int o = 1; o < 32; o <<= 1) {
            float va = __shfl_up_sync(FULLM, ainc, o);
            float vb = __shfl_up_sync(FULLM, binc, o);
            if (lane >= o) { ainc += va; binc += vb; }
        }
        if (lane == 31) { wA[wid] = ainc; wB[wid] = binc; }
        __syncthreads();
        float baseA = 0.f, baseB = 0.f;
        for (int w = 0; w < wid; w++) { baseA += wA[w]; baseB += wB[w]; }
        float aex = baseA + ainc - la;
        float bex = baseB + binc - lb;
        if (i0 + 3 < 993) {
            ((float4*)xv)[tid] =
                make_float4(aex + av[0], aex + av[1], aex + av[2], aex + av[3]);
            ((float4*)xv)[256 + tid] =
                make_float4(bex + bv[0], bex + bv[1], bex + bv[2], bex + bv[3]);
        } else {
#pragma unroll
            for (int u = 0; u < 4; u++) {
                int i = i0 + u;
                if (i < 993) {
                    xv[i]        = aex + av[u];
                    xv[1024 + i] = bex + bv[u];
                }
            }
        }
        __syncthreads();
        if (tid == 0) {
            float tot = xv[992];
            s_total   = tot;
            s_inv     = 1.0f / sqrtf(tot);
            s_tot2raw = xv[1024 + 992];
        }
        __syncthreads();
    }

    // ---- 8. edges: searchsorted(si, k/16*total, 'right'), clip ----------
    if (tid < 17) {
        float v = ((float)tid * (1.0f / 16.0f)) * s_total;
        int lo = 0, hi = 993;
        while (lo < hi) {
            int mid = (lo + hi) >> 1;
            if (xv[mid] <= v) lo = mid + 1; else hi = mid;
        }
        if (lo > 992) lo = 992;
        s_edges[tid] = lo;
    }
    __syncthreads();

    // ---- 9. chisq + final loss ------------------------------------------
    if (tid == 0) {
        float b = wmax[0];
#pragma unroll
        for (int w = 1; w < 7; w++) b = fmaxf(b, wmax[w]);
        float lossbase = (1.0f - b) / (1.0f + b);
        float inv = s_inv;
        float total2 = s_tot2raw * inv;
        float mean = total2 * (1.0f / 16.0f);
        float ssum = 0.f;
        for (int k = 0; k < 16; k++) {
            float r = xv[1024 + s_edges[k + 1]] * inv;
            float l = xv[1024 + s_edges[k]] * inv;
            float d = (r - l) - mean;
            ssum += d * d;
        }
        float chisq = 16.0f * ssum * (1.0f / 15.0f);
        float c3 = chisq * chisq * chisq;
        out[row] = lossbase * powf(1.0f + c3, 1.0f / 6.0f);
    }
}

extern "C" void kernel_launch(void* const* d_in, const int* in_sizes, int n_in,
                              void* d_out, int out_size)
{
    const float* x_hat = (const float*)d_in[0];
    const float* x     = (const float*)d_in[1];
    float* out = (float*)d_out;
    mfl_kernel<<<512, 256>>>(x_hat, x, out);
}

// round 12
// speedup vs baseline: 1.0152x; 1.0152x over previous
#include <cuda_runtime.h>
#include <math.h>
#include <cstring>

// MatchedFilterLoss fused kernel for GB300 (sm_103a)
// Single kernel: 512 blocks x 256 threads. Pearson computed spectrally.
// FFT#1: 2048-pt radix-8 (stage-1 from registers, register twiddles).
// FFT#2: Hermitian->real via half-size 1024-pt complex FFT (radix-4 x5).
// Shared addresses: zs(base) ^ compile-time XOR constants.
// Complex add/sub: packed f32x2 PTX ops.
// xh/yc kept ONLY at boundaries (all interior stores were dead).

#define NTH 256
#define FULLM 0xffffffffu

// storage position of natural frequency k after radix-[8,8,8,4] DIF (2048)
__device__ __forceinline__ int fpos8(int k)
{
    return ((k & 7) << 8) | (((k >> 3) & 7) << 5) | (((k >> 6) & 7) << 2) | (k >> 9);
}

// storage position of frequency m after radix-[4,4,4,4,4] DIF (1024)
__device__ __forceinline__ int rev4(int m)
{
    return ((m & 3) << 8) | (((m >> 2) & 3) << 6) | (((m >> 4) & 3) << 4)
         | (((m >> 6) & 3) << 2) | (m >> 8);
}

// bank swizzle for float2 array z (XOR-linear)
__device__ __forceinline__ int zs(int p)
{
    return p ^ ((p >> 4) & 15) ^ ((p >> 8) & 7) ^ (((p >> 6) & 1) << 3);
}
// constexpr version for compile-time offset constants
__device__ constexpr int zc(int m)
{
    return m ^ ((m >> 4) & 15) ^ ((m >> 8) & 7) ^ (((m >> 6) & 1) << 3);
}

// ---- packed f32x2 complex add/sub (single instruction each) -------------
__device__ __forceinline__ unsigned long long f2u(float2 a)
{
    unsigned long long u; memcpy(&u, &a, 8); return u;
}
__device__ __forceinline__ float2 u2f(unsigned long long u)
{
    float2 a; memcpy(&a, &u, 8); return a;
}
__device__ __forceinline__ float2 c_add(float2 a, float2 b)
{
    unsigned long long r;
    asm("add.rn.f32x2 %0, %1, %2;" : "=l"(r) : "l"(f2u(a)), "l"(f2u(b)));
    return u2f(r);
}
__device__ __forceinline__ float2 c_sub(float2 a, float2 b)
{
    unsigned long long r;
    asm("sub.rn.f32x2 %0, %1, %2;" : "=l"(r) : "l"(f2u(a)), "l"(f2u(b)));
    return u2f(r);
}

__device__ __forceinline__ float2 cmul2(float2 a, float2 w)
{
    return make_float2(a.x*w.x - a.y*w.y, a.x*w.y + a.y*w.x);
}

// w_2048^e = exp(-i*pi*e/1024)
__device__ __forceinline__ float2 tw2048(int e)
{
    float2 w;
    sincospif(-(float)e * (1.0f / 1024.0f), &w.y, &w.x);
    return w;
}

// radix-8 DIF butterfly
__device__ __forceinline__ void radix8_core(float2* x)
{
    const float H = 0.70710678118654752f;
    float2 a0=c_add(x[0],x[4]), d0=c_sub(x[0],x[4]);
    float2 a1=c_add(x[1],x[5]), d1=c_sub(x[1],x[5]);
    float2 a2=c_add(x[2],x[6]), d2=c_sub(x[2],x[6]);
    float2 a3=c_add(x[3],x[7]), d3=c_sub(x[3],x[7]);
    float2 b0=d0;
    float2 b1=make_float2(H*(d1.x+d1.y), H*(d1.y-d1.x));
    float2 b2=make_float2(d2.y, -d2.x);
    float2 b3=make_float2(H*(d3.y-d3.x), -H*(d3.x+d3.y));
    float2 t0=c_add(a0,a2), t1=c_add(a1,a3), t2=c_sub(a0,a2);
    float2 u =c_sub(a1,a3); float2 t3=make_float2(u.y,-u.x);
    x[0]=c_add(t0,t1); x[2]=c_add(t2,t3); x[4]=c_sub(t0,t1); x[6]=c_sub(t2,t3);
    t0=c_add(b0,b2); t1=c_add(b1,b3); t2=c_sub(b0,b2);
    u=c_sub(b1,b3); t3=make_float2(u.y,-u.x);
    x[1]=c_add(t0,t1); x[3]=c_add(t2,t3); x[5]=c_sub(t0,t1); x[7]=c_sub(t2,t3);
}

// store radix-8 outputs at precomputed addresses; twiddles chained from w1
__device__ __forceinline__ void bfly8_store_ad(float2* z, const float2* x, const int* ad, float2 w1)
{
    float2 w2 = cmul2(w1, w1);
    float2 w3 = cmul2(w2, w1);
    float2 w4 = cmul2(w2, w2);
    float2 w5 = cmul2(w2, w3);
    float2 w6 = cmul2(w3, w3);
    float2 w7 = cmul2(w3, w4);
    z[ad[0]] = x[0];
    z[ad[1]] = cmul2(x[1], w1);
    z[ad[2]] = cmul2(x[2], w2);
    z[ad[3]] = cmul2(x[3], w3);
    z[ad[4]] = cmul2(x[4], w4);
    z[ad[5]] = cmul2(x[5], w5);
    z[ad[6]] = cmul2(x[6], w6);
    z[ad[7]] = cmul2(x[7], w7);
}

template<int Q>
__device__ __forceinline__ void stage8_z(float2* z, int tid, float2 w1)
{
    const int j    = tid & (Q - 1);
    const int base = (tid / Q) * (Q * 8) + j;
    const int pb   = zs(base);
    int ad[8];
#pragma unroll
    for (int s = 0; s < 8; s++) ad[s] = pb ^ zc(Q * s);
    float2 x[8];
#pragma unroll
    for (int s = 0; s < 8; s++) x[s] = z[ad[s]];
    radix8_core(x);
    bfly8_store_ad(z, x, ad, w1);
}

// radix-4 DIF butterfly (in place)
__device__ __forceinline__ void radix4_core(float2* x)
{
    float2 t0=c_add(x[0],x[2]), t1=c_add(x[1],x[3]), t2=c_sub(x[0],x[2]);
    float2 u =c_sub(x[1],x[3]); float2 t3=make_float2(u.y,-u.x);
    x[0]=c_add(t0,t1); x[1]=c_add(t2,t3); x[2]=c_sub(t0,t1); x[3]=c_sub(t2,t3);
}

__device__ __forceinline__ void bfly4_store_ad(float2* z, const float2* x, const int* ad, float2 w1)
{
    float2 w2 = cmul2(w1, w1), w3 = cmul2(w2, w1);
    z[ad[0]] = x[0];
    z[ad[1]] = cmul2(x[1], w1);
    z[ad[2]] = cmul2(x[2], w2);
    z[ad[3]] = cmul2(x[3], w3);
}

__global__ __launch_bounds__(256, 4)
void mfl_kernel(const float* __restrict__ xhat_g,
                const float* __restrict__ x_g,
                float* __restrict__ out)
{
    __shared__ __align__(16) float xh[2048];   // centered x_hat (boundaries only)
    __shared__ __align__(16) float yc[2048];   // centered x (boundaries only)
    __shared__ __align__(16) float xv[2048];   // integrands a|cm, then cumsums
    __shared__ float2 z[2048];                 // FFT workspace (bank-swizzled)
    __shared__ float P1[52], P2[52], Q1[52], Q2[52];
    __shared__ __align__(16) float red1[24];
    __shared__ __align__(16) float red2[24];
    __shared__ float wA[8], wB[8];
    __shared__ float wmax[7];
    __shared__ float s_T1, s_T2, s_Vy;
    __shared__ float s_total, s_tot2raw, s_inv;
    __shared__ int   s_edges[17];

    const int tid  = threadIdx.x;
    const int lane = tid & 31;
    const int wid  = tid >> 5;
    const int row  = blockIdx.x;

    const float* xh_in = xhat_g + (size_t)row * 2048;
    const float* x_in  = x_g    + (size_t)row * 2048;

    // per-thread twiddles, computed once
    float2 twA = tw2048(tid);               // 2048 FFT Q=256 stage + twist base
    float2 twB = tw2048(8 * (tid & 31));    // 2048 FFT Q=32
    float2 twC = tw2048(64 * (tid & 3));    // 2048 FFT Q=4
    float2 twE = tw2048(8 * (tid & 63));    // 1024 FFT stage1 (Q=64)
    float2 twF = tw2048(32 * (tid & 15));   // 1024 FFT stage2 (Q=16)
    float2 twG = tw2048(128 * (tid >> 6));  // 1024 FFT stage3 (Q=4, j=tid>>6)

    // ---- 1. register-resident load + min/max/mean ------------------------
    float hr[8], xr[8];
#pragma unroll
    for (int s = 0; s < 8; s++) {
        hr[s] = xh_in[tid + 256 * s];
        xr[s] = x_in[tid + 256 * s];
    }
    float mn, mx, my;
    {
        float pmn = 1e30f, pmx = -1e30f, psy = 0.f;
#pragma unroll
        for (int s = 0; s < 8; s++) {
            pmn = fminf(pmn, hr[s]); pmx = fmaxf(pmx, hr[s]); psy += xr[s];
        }
        for (int o = 16; o; o >>= 1) {
            pmn = fminf(pmn, __shfl_xor_sync(FULLM, pmn, o));
            pmx = fmaxf(pmx, __shfl_xor_sync(FULLM, pmx, o));
            psy += __shfl_xor_sync(FULLM, psy, o);
        }
        if (lane == 0) { red1[wid] = pmn; red1[8 + wid] = pmx; red1[16 + wid] = psy; }
        __syncthreads();
        // vectorized fold (6 x LDS.128 broadcast)
        const float4* r4 = (const float4*)red1;
        float4 m0 = r4[0], m1 = r4[1], x0 = r4[2], x1 = r4[3], y0 = r4[4], y1 = r4[5];
        mn = fminf(fminf(fminf(m0.x, m0.y), fminf(m0.z, m0.w)),
                   fminf(fminf(m1.x, m1.y), fminf(m1.z, m1.w)));
        mx = fmaxf(fmaxf(fmaxf(x0.x, x0.y), fmaxf(x0.z, x0.w)),
                   fmaxf(fmaxf(x1.x, x1.y), fmaxf(x1.z, x1.w)));
        my = (y0.x + y0.y + y0.z + y0.w + y1.x + y1.y + y1.z + y1.w) * (1.0f / 2048.0f);
    }

    // ---- 2. center in regs, totals; store ONLY boundary xh/yc ------------
    {
        float inv = 1.0f / (mx - mn);
        float t1 = 0.f, t2 = 0.f, vy = 0.f;
#pragma unroll
        for (int s = 0; s < 8; s++) {
            float h = 2.0f * (hr[s] - mn) * inv - 1.0f;
            hr[s] = h;
            float y = xr[s] - my;
            t1 += h; t2 += h * h; vy += y * y;
        }
        // boundary stores: xh/yc only read at [0..51] and [1996..2047]
        if (tid < 52)   { xh[tid] = hr[0];        yc[tid] = xr[0] - my; }
        if (tid >= 204) { xh[1792 + tid] = hr[7]; yc[1792 + tid] = xr[7] - my; }
        for (int o = 16; o; o >>= 1) {
            t1 += __shfl_xor_sync(FULLM, t1, o);
            t2 += __shfl_xor_sync(FULLM, t2, o);
            vy += __shfl_xor_sync(FULLM, vy, o);
        }
        if (lane == 0) { red2[wid] = t1; red2[8 + wid] = t2; red2[16 + wid] = vy; }
        __syncthreads();
    }

    // ---- 3. FFT#1 stage 1 from registers; P/Q prefix scans; totals fold --
    {
        float2 x[8];
#pragma unroll
        for (int s = 0; s < 8; s++) x[s] = make_float2(hr[s], xr[s]);
        radix8_core(x);
        {
            const int pb = zs(tid);
            int ad[8];
#pragma unroll
            for (int s = 0; s < 8; s++) ad[s] = pb ^ zc(256 * s);
            bfly8_store_ad(z, x, ad, twA);
        }

        // P (head) and Q (tail) prefix sums as warp scans; totals on warp 2
        if (wid == 0) {
            float a0 = 0.f, a1 = 0.f;
            if (lane < 26) { float2 v = ((const float2*)xh)[lane]; a0 = v.x; a1 = v.y; }
            float s1 = a0 + a1, s2 = a0 * a0 + a1 * a1;
            float i1 = s1, i2 = s2;
            for (int o = 1; o < 32; o <<= 1) {
                float u1 = __shfl_up_sync(FULLM, i1, o);
                float u2 = __shfl_up_sync(FULLM, i2, o);
                if (lane >= o) { i1 += u1; i2 += u2; }
            }
            if (lane < 26) {
                float e1 = i1 - s1, e2 = i2 - s2;
                P1[2*lane] = e1;  P1[2*lane+1] = e1 + a0;
                P2[2*lane] = e2;  P2[2*lane+1] = e2 + a0 * a0;
            }
        } else if (wid == 1) {
            float b0 = 0.f, b1 = 0.f;
            if (lane < 26) {
                float2 v = ((const float2*)xh)[1023 - lane];  // {xh[2046-2l], xh[2047-2l]}
                b0 = v.y; b1 = v.x;
            }
            float s1 = b0 + b1, s2 = b0 * b0 + b1 * b1;
            float i1 = s1, i2 = s2;
            for (int o = 1; o < 32; o <<= 1) {
                float u1 = __shfl_up_sync(FULLM, i1, o);
                float u2 = __shfl_up_sync(FULLM, i2, o);
                if (lane >= o) { i1 += u1; i2 += u2; }
            }
            if (lane < 26) {
                float e1 = i1 - s1, e2 = i2 - s2;
                Q1[2*lane] = e1;  Q1[2*lane+1] = e1 + b0;
                Q2[2*lane] = e2;  Q2[2*lane+1] = e2 + b0 * b0;
            }
        } else if (wid == 2 && lane < 3) {
            const float* src = red2 + 8 * lane;
            float t = src[0] + src[1] + src[2] + src[3]
                    + src[4] + src[5] + src[6] + src[7];
            if (lane == 0) s_T1 = t;
            else if (lane == 1) s_T2 = t;
            else s_Vy = t;
        }
        __syncthreads();
    }
    stage8_z<32>(z, tid, twB); __syncthreads();
    stage8_z<4>(z, tid, twC);  __syncthreads();
    // final radix-4 of FFT#1
#pragma unroll
    for (int it = 0; it < 2; it++) {
        int pb = zs(4 * (tid + it * 256));
        float2 x[4];
#pragma unroll
        for (int r = 0; r < 4; r++) x[r] = z[pb ^ r];
        radix4_core(x);
#pragma unroll
        for (int r = 0; r < 4; r++) z[pb ^ r] = x[r];
    }
    __syncthreads();

    // ---- 4. untangle: chisq integrands; write P[k] into z[0..1024] -------
    {
        const int zsC[4] = { 0, 17, 1, 16 };   // zs0(fpos8(256*it))
        const int zsW[4] = { 18, 3, 19, 2 };   // zs0(fpos8(256*(7-it)))
        const int azS[4] = { 17, 1, 16, 2 };   // tid==255: zs(fpos8(256*(1+it)))
        const int pz = zs(fpos8(1 + tid));
        const int pw = zs(fpos8(255 - tid));
        const int pk = zs(1 + tid);
        float2 Pk[4];
#pragma unroll
        for (int it = 0; it < 4; it++) {
            int k  = 1 + tid + it * 256;         // 1..1024
            int aZ = (tid == 255) ? azS[it] : (pz ^ zsC[it]);
            int aW = pw ^ zsW[it];
            float2 Z = z[aZ];
            float2 W = z[aW];
            const float sc = 0.5f / 2048.0f;
            float h_r = (Z.x + W.x) * sc, h_i = (Z.y - W.y) * sc;
            float s_r = (Z.y + W.y) * sc, s_i = (W.x - Z.x) * sc;
            float pr = h_r * s_r + h_i * s_i;
            float pi = h_i * s_r - h_r * s_i;
            if (k >= 32) {
                float a  = 4.0f * (h_r * h_r + h_i * h_i);
                float cm = 4.0f * sqrtf(pr * pr + pi * pi);
                xv[k - 32]        = a;
                xv[1024 + k - 32] = cm;
            }
            Pk[it] = make_float2(pr, pi);
        }
        __syncthreads();                         // all reads of FFT#1 output done
#pragma unroll
        for (int it = 0; it < 4; it++) {
            int aP = (tid == 255) ? (257 * (1 + it)) : (pk ^ (257 * it));
            z[aP] = Pk[it];
        }
        if (tid == 0) z[0] = make_float2(0.f, 0.f);   // zs(0)=0: P[0] := 0
        __syncthreads();
    }

    // ---- 5. FFT#2: Hermitian->real via 1024-pt complex FFT ---------------
    {
        const float Hc = 0.70710678118654752f;
        float2 V[4];
        {
            const int pa  = zs(tid);
            const int pb2 = (tid == 0) ? 0 : zs(256 - tid);
            float2 a[4], b[4];
#pragma unroll
            for (int s = 0; s < 4; s++) {
                a[s] = z[pa ^ (257 * s)];
                b[s] = (tid == 0) ? z[257 * (4 - s)] : z[pb2 ^ (257 * (3 - s))];
            }
#pragma unroll
            for (int s = 0; s < 4; s++) {
                float2 w8s = (s == 0) ? make_float2(1.f, 0.f)
                           : (s == 1) ? make_float2(Hc, -Hc)
                           : (s == 2) ? make_float2(0.f, -1.f)
                                      : make_float2(-Hc, -Hc);
                float2 ca  = make_float2(a[s].x, -a[s].y);
                float2 sum = c_add(ca, b[s]);
                float2 dif = c_sub(ca, b[s]);
                float2 twk = cmul2(twA, w8s);         // e^{-i pi k/1024}
                float2 idt = cmul2(dif, twk);
                V[s] = make_float2(sum.x - idt.y, sum.y + idt.x);
            }
            __syncthreads();                      // all P reads done before overwrite
            radix4_core(V);
            float2 w1 = cmul2(twA, twA);          // w_1024^tid
            int ad[4];
#pragma unroll
            for (int r = 0; r < 4; r++) ad[r] = pa ^ zc(256 * r);
            bfly4_store_ad(z, V, ad, w1);
            __syncthreads();
        }
        // stage 1: Q=64
        {
            int base = (tid >> 6) * 256 + (tid & 63);
            int pb = zs(base);
            int ad[4];
#pragma unroll
            for (int r = 0; r < 4; r++) ad[r] = pb ^ zc(64 * r);
            float2 x[4];
#pragma unroll
            for (int r = 0; r < 4; r++) x[r] = z[ad[r]];
            radix4_core(x);
            bfly4_store_ad(z, x, ad, twE);
            __syncthreads();
        }
        // stage 2: Q=16
        {
            int base = (tid >> 4) * 64 + (tid & 15);
            int pb = zs(base);
            int ad[4];
#pragma unroll
            for (int r = 0; r < 4; r++) ad[r] = pb ^ zc(16 * r);
            float2 x[4];
#pragma unroll
            for (int r = 0; r < 4; r++) x[r] = z[ad[r]];
            radix4_core(x);
            bfly4_store_ad(z, x, ad, twF);
            __syncthreads();
        }
        // stage 3: Q=4 (j = tid>>6 remap keeps banks conflict-free)
        {
            int base = (tid & 63) * 16 + (tid >> 6);
            int pb = zs(base);
            int ad[4];
#pragma unroll
            for (int r = 0; r < 4; r++) ad[r] = pb ^ zc(4 * r);
            float2 x[4];
#pragma unroll
            for (int r = 0; r < 4; r++) x[r] = z[ad[r]];
            radix4_core(x);
            bfly4_store_ad(z, x, ad, twG);
            __syncthreads();
        }
        // stage 4 (final, untwiddled) pruned to quads feeding needed outputs
        {
            int b = tid;
            int m0 = ((b & 3) << 6) | (((b >> 2) & 3) << 4) | (((b >> 4) & 3) << 2) | (b >> 6);
            if (m0 <= 25 || m0 >= 230) {
                int pb = zs(4 * b);
                float2 x[4];
#pragma unroll
                for (int r = 0; r < 4; r++) x[r] = z[pb ^ r];
                radix4_core(x);
#pragma unroll
                for (int r = 0; r < 4; r++) z[pb ^ r] = x[r];
            }
            __syncthreads();
        }
    }

    // ---- 6. circular->linear corrections, Pearson corr, max -------------
    // (no barrier after: scan below touches disjoint state, warp 7 overlaps)
    if (tid < 224) {                      // warps 0..6, 2 threads per shift
        const int pid = tid >> 1;
        const int h   = tid & 1;
        const bool act = (pid < 103);
        float wrap = 0.f, rc = 0.f;
        int d = 0;
        if (act) {
            d = pid - 51;
            int dc = d & 2047;
            int m  = dc >> 1;
            float2 val = z[zs(rev4(m))];
            rc = 2048.0f * ((dc & 1) ? val.y : val.x);
            if (d > 0) {
                for (int t = h; t < d; t += 2) wrap += xh[t] * yc[2048 - d + t];
            } else if (d < 0) {
                int mm = -d;
                for (int t = h; t < mm; t += 2) wrap += xh[2048 - mm + t] * yc[t];
            }
        }
        wrap += __shfl_xor_sync(FULLM, wrap, 1);
        float corr = -2.f;
        if (act) {
            float T1 = s_T1, T2 = s_T2, Vy = s_Vy;
            float acc = rc - wrap;
            float S1, S2v;
            if (d >= 0) { S1 = T1 - P1[d];  S2v = T2 - P2[d]; }
            else        { S1 = T1 - Q1[-d]; S2v = T2 - Q2[-d]; }
            float varx = S2v - S1 * S1 * (1.0f / 2048.0f);
            corr = acc / sqrtf(varx * Vy);
        }
        for (int o = 16; o; o >>= 1)
            corr = fmaxf(corr, __shfl_xor_sync(FULLM, corr, o));
        if (lane == 0) wmax[wid] = corr;
    }

    // ---- 7. dual parallel inclusive scan over 993 elements --------------
    {
        const int i0 = tid * 4;
        float4 a4 = ((const float4*)xv)[tid];
        float4 b4 = ((const float4*)xv)[256 + tid];
        float av[4] = { a4.x, a4.y, a4.z, a4.w };
        float bv[4] = { b4.x, b4.y, b4.z, b4.w };
#pragma unroll
        for (int u = 0; u < 4; u++) {
            if (i0 + u >= 993) { av[u] = 0.f; bv[u] = 0.f; }
        }
        av[1] += av[0]; av[2] += av[1]; av[3] += av[2];
        bv[1] += bv[0]; bv[2] += bv[1]; bv[3] += bv[2];
        float la = av[3], lb = bv[3];
        float ainc = la, binc = lb;
#pragma unroll
        for (int o = 1; o < 32; o <<= 1) {
            float va = __shfl_up_sync(FULLM, ainc, o);
            float vb = __shfl_up_sync(FULLM, binc, o);
            if (lane >= o) { ainc += va; binc += vb; }
        }
        if (lane == 31) { wA[wid] = ainc; wB[wid] = binc; }
        __syncthreads();
        float baseA = 0.f, baseB = 0.f;
        for (int w = 0; w < wid; w++) { baseA += wA[w]; baseB += wB[w]; }
        float aex = baseA + ainc - la;
        float bex = baseB + binc - lb;
        if (i0 + 3 < 993) {
            ((float4*)xv)[tid] =
                make_float4(aex + av[0], aex + av[1], aex + av[2], aex + av[3]);
            ((float4*)xv)[256 + tid] =
                make_float4(bex + bv[0], bex + bv[1], bex + bv[2], bex + bv[3]);
        } else {
#pragma unroll
            for (int u = 0; u < 4; u++) {
                int i = i0 + u;
                if (i < 993) {
                    xv[i]        = aex + av[u];
                    xv[1024 + i] = bex + bv[u];
                }
            }
        }
        __syncthreads();
        if (tid == 0) {
            float tot = xv[992];
            s_total   = tot;
            s_inv     = 1.0f / sqrtf(tot);
            s_tot2raw = xv[1024 + 992];
        }
        __syncwarp();      // warp-0-only tail from here on
    }

    // ---- 8. edges: searchsorted(si, k/16*total, 'right'), clip ----------
    if (tid < 17) {
        float v = ((float)tid * (1.0f / 16.0f)) * s_total;
        int lo = 0, hi = 993;
        while (lo < hi) {
            int mid = (lo + hi) >> 1;
            if (xv[mid] <= v) lo = mid + 1; else hi = mid;
        }
        if (lo > 992) lo = 992;
        s_edges[tid] = lo;
    }
    __syncwarp();

    // ---- 9. chisq + final loss ------------------------------------------
    if (tid == 0) {
        float b = wmax[0];
#pragma unroll
        for (int w = 1; w < 7; w++) b = fmaxf(b, wmax[w]);
        float lossbase = (1.0f - b) / (1.0f + b);
        float inv = s_inv;
        float total2 = s_tot2raw * inv;
        float mean = total2 * (1.0f / 16.0f);
        float ssum = 0.f;
        for (int k = 0; k < 16; k++) {
            float r = xv[1024 + s_edges[k + 1]] * inv;
            float l = xv[1024 + s_edges[k]] * inv;
            float d = (r - l) - mean;
            ssum += d * d;
        }
        float chisq = 16.0f * ssum * (1.0f / 15.0f);
        float c3 = chisq * chisq * chisq;
        out[row] = lossbase * powf(1.0f + c3, 1.0f / 6.0f);
    }
}

extern "C" void kernel_launch(void* const* d_in, const int* in_sizes, int n_in,
                              void* d_out, int out_size)
{
    const float* x_hat = (const float*)d_in[0];
    const float* x     = (const float*)d_in[1];
    float* out = (float*)d_out;
    mfl_kernel<<<512, 256>>>(x_hat, x, out);
}

// round 14
// speedup vs baseline: 1.0368x; 1.0213x over previous
#include <cuda_runtime.h>
#include <math.h>
#include <cstring>

// MatchedFilterLoss fused kernel for GB300 (sm_103a)
// Single kernel: 512 blocks x 256 threads. Pearson computed spectrally.
// FFT#1: 2048-pt radix-8 (stage-1 from registers, register twiddles).
// FFT#2: Hermitian->real via half-size 1024-pt complex FFT (radix-4 x5);
//        stage 0 ping-pongs into z's upper half (one barrier deleted).
// Shared addresses: zs(base) ^ compile-time XOR constants.
// Complex add/sub: packed f32x2 PTX ops. 3 of 6 twiddles are constants.

#define NTH 256
#define FULLM 0xffffffffu

__device__ __forceinline__ int fpos8(int k)
{
    return ((k & 7) << 8) | (((k >> 3) & 7) << 5) | (((k >> 6) & 7) << 2) | (k >> 9);
}

__device__ __forceinline__ int rev4(int m)
{
    return ((m & 3) << 8) | (((m >> 2) & 3) << 6) | (((m >> 4) & 3) << 4)
         | (((m >> 6) & 3) << 2) | (m >> 8);
}

// bank swizzle for float2 array z (XOR-linear); maps [0,1024)->[0,1024)
__device__ __forceinline__ int zs(int p)
{
    return p ^ ((p >> 4) & 15) ^ ((p >> 8) & 7) ^ (((p >> 6) & 1) << 3);
}
__device__ constexpr int zc(int m)
{
    return m ^ ((m >> 4) & 15) ^ ((m >> 8) & 7) ^ (((m >> 6) & 1) << 3);
}

// ---- packed f32x2 complex add/sub --------------------------------------
__device__ __forceinline__ unsigned long long f2u(float2 a)
{
    unsigned long long u; memcpy(&u, &a, 8); return u;
}
__device__ __forceinline__ float2 u2f(unsigned long long u)
{
    float2 a; memcpy(&a, &u, 8); return a;
}
__device__ __forceinline__ float2 c_add(float2 a, float2 b)
{
    unsigned long long r;
    asm("add.rn.f32x2 %0, %1, %2;" : "=l"(r) : "l"(f2u(a)), "l"(f2u(b)));
    return u2f(r);
}
__device__ __forceinline__ float2 c_sub(float2 a, float2 b)
{
    unsigned long long r;
    asm("sub.rn.f32x2 %0, %1, %2;" : "=l"(r) : "l"(f2u(a)), "l"(f2u(b)));
    return u2f(r);
}

__device__ __forceinline__ float2 cmul2(float2 a, float2 w)
{
    return make_float2(a.x*w.x - a.y*w.y, a.x*w.y + a.y*w.x);
}

// w_2048^e = exp(-i*pi*e/1024)
__device__ __forceinline__ float2 tw2048(int e)
{
    float2 w;
    sincospif(-(float)e * (1.0f / 1024.0f), &w.y, &w.x);
    return w;
}

// radix-8 DIF butterfly
__device__ __forceinline__ void radix8_core(float2* x)
{
    const float H = 0.70710678118654752f;
    float2 a0=c_add(x[0],x[4]), d0=c_sub(x[0],x[4]);
    float2 a1=c_add(x[1],x[5]), d1=c_sub(x[1],x[5]);
    float2 a2=c_add(x[2],x[6]), d2=c_sub(x[2],x[6]);
    float2 a3=c_add(x[3],x[7]), d3=c_sub(x[3],x[7]);
    float2 b0=d0;
    float2 b1=make_float2(H*(d1.x+d1.y), H*(d1.y-d1.x));
    float2 b2=make_float2(d2.y, -d2.x);
    float2 b3=make_float2(H*(d3.y-d3.x), -H*(d3.x+d3.y));
    float2 t0=c_add(a0,a2), t1=c_add(a1,a3), t2=c_sub(a0,a2);
    float2 u =c_sub(a1,a3); float2 t3=make_float2(u.y,-u.x);
    x[0]=c_add(t0,t1); x[2]=c_add(t2,t3); x[4]=c_sub(t0,t1); x[6]=c_sub(t2,t3);
    t0=c_add(b0,b2); t1=c_add(b1,b3); t2=c_sub(b0,b2);
    u=c_sub(b1,b3); t3=make_float2(u.y,-u.x);
    x[1]=c_add(t0,t1); x[3]=c_add(t2,t3); x[5]=c_sub(t0,t1); x[7]=c_sub(t2,t3);
}

__device__ __forceinline__ void bfly8_store_ad(float2* z, const float2* x, const int* ad, float2 w1)
{
    float2 w2 = cmul2(w1, w1);
    float2 w3 = cmul2(w2, w1);
    float2 w4 = cmul2(w2, w2);
    float2 w5 = cmul2(w2, w3);
    float2 w6 = cmul2(w3, w3);
    float2 w7 = cmul2(w3, w4);
    z[ad[0]] = x[0];
    z[ad[1]] = cmul2(x[1], w1);
    z[ad[2]] = cmul2(x[2], w2);
    z[ad[3]] = cmul2(x[3], w3);
    z[ad[4]] = cmul2(x[4], w4);
    z[ad[5]] = cmul2(x[5], w5);
    z[ad[6]] = cmul2(x[6], w6);
    z[ad[7]] = cmul2(x[7], w7);
}

template<int Q>
__device__ __forceinline__ void stage8_z(float2* z, int tid, float2 w1)
{
    const int j    = tid & (Q - 1);
    const int base = (tid / Q) * (Q * 8) + j;
    const int pb   = zs(base);
    int ad[8];
#pragma unroll
    for (int s = 0; s < 8; s++) ad[s] = pb ^ zc(Q * s);
    float2 x[8];
#pragma unroll
    for (int s = 0; s < 8; s++) x[s] = z[ad[s]];
    radix8_core(x);
    bfly8_store_ad(z, x, ad, w1);
}

__device__ __forceinline__ void radix4_core(float2* x)
{
    float2 t0=c_add(x[0],x[2]), t1=c_add(x[1],x[3]), t2=c_sub(x[0],x[2]);
    float2 u =c_sub(x[1],x[3]); float2 t3=make_float2(u.y,-u.x);
    x[0]=c_add(t0,t1); x[1]=c_add(t2,t3); x[2]=c_sub(t0,t1); x[3]=c_sub(t2,t3);
}

__device__ __forceinline__ void bfly4_store_ad(float2* z, const float2* x, const int* ad, float2 w1)
{
    float2 w2 = cmul2(w1, w1), w3 = cmul2(w2, w1);
    z[ad[0]] = x[0];
    z[ad[1]] = cmul2(x[1], w1);
    z[ad[2]] = cmul2(x[2], w2);
    z[ad[3]] = cmul2(x[3], w3);
}

__global__ __launch_bounds__(256, 4)
void mfl_kernel(const float* __restrict__ xhat_g,
                const float* __restrict__ x_g,
                float* __restrict__ out)
{
    __shared__ __align__(16) float xh[2048];   // centered x_hat (boundaries only)
    __shared__ __align__(16) float yc[2048];   // centered x (boundaries only)
    __shared__ __align__(16) float xv[2048];   // integrands a|cm, then cumsums
    __shared__ float2 z[2048];                 // FFT workspace (bank-swizzled)
    __shared__ float P1[52], P2[52], Q1[52], Q2[52];
    __shared__ __align__(16) float red1[24];
    __shared__ __align__(16) float red2[24];
    __shared__ float2 wAB[8];
    __shared__ float wmax[7];
    __shared__ float2 s_P1024;                 // relocated P[1024] (Nyquist)
    __shared__ float s_T1, s_T2, s_Vy;
    __shared__ float s_total, s_tot2raw, s_inv;
    __shared__ int   s_edges[17];

    const int tid  = threadIdx.x;
    const int lane = tid & 31;
    const int wid  = tid >> 5;
    const int row  = blockIdx.x;

    const float* xh_in = xhat_g + (size_t)row * 2048;
    const float* x_in  = x_g    + (size_t)row * 2048;

    // per-thread twiddles: 3 sincospif + 3 derived/constant
    float2 twA = tw2048(tid);               // 2048 FFT Q=256 stage + twist base
    float2 twE = tw2048(8 * (tid & 63));    // 1024 FFT stage1 (Q=64)
    float2 twF = tw2048(32 * (tid & 15));   // 1024 FFT stage2 (Q=16)
    // twB = tw(8*(tid&31)) = twE * exp(+i pi/4) when tid&32 else twE
    float2 twB = (tid & 32)
        ? cmul2(twE, make_float2(0.70710678118654752f, 0.70710678118654752f))
        : twE;
    // twC = tw(64*(tid&3)): angles {0, pi/16, pi/8, 3pi/16}
    int cc = tid & 3;
    float2 twC = (cc == 0) ? make_float2(1.f, 0.f)
               : (cc == 1) ? make_float2(0.98078528040323044f, -0.19509032201612827f)
               : (cc == 2) ? make_float2(0.92387953251128676f, -0.38268343236508977f)
                           : make_float2(0.83146961230254524f, -0.55557023301960222f);
    // twG = tw(128*(tid>>6)): angles {0, pi/8, pi/4, 3pi/8}
    int gg = tid >> 6;
    float2 twG = (gg == 0) ? make_float2(1.f, 0.f)
               : (gg == 1) ? make_float2(0.92387953251128676f, -0.38268343236508977f)
               : (gg == 2) ? make_float2(0.70710678118654752f, -0.70710678118654752f)
                           : make_float2(0.38268343236508977f, -0.92387953251128676f);

    // ---- 1. register-resident load + min/max/mean ------------------------
    float hr[8], xr[8];
#pragma unroll
    for (int s = 0; s < 8; s++) {
        hr[s] = xh_in[tid + 256 * s];
        xr[s] = x_in[tid + 256 * s];
    }
    float mn, mx, my;
    {
        float pmn = 1e30f, pmx = -1e30f, psy = 0.f;
#pragma unroll
        for (int s = 0; s < 8; s++) {
            pmn = fminf(pmn, hr[s]); pmx = fmaxf(pmx, hr[s]); psy += xr[s];
        }
        for (int o = 16; o; o >>= 1) {
            pmn = fminf(pmn, __shfl_xor_sync(FULLM, pmn, o));
            pmx = fmaxf(pmx, __shfl_xor_sync(FULLM, pmx, o));
            psy += __shfl_xor_sync(FULLM, psy, o);
        }
        if (lane == 0) { red1[wid] = pmn; red1[8 + wid] = pmx; red1[16 + wid] = psy; }
        __syncthreads();
        const float4* r4 = (const float4*)red1;
        float4 m0 = r4[0], m1 = r4[1], x0 = r4[2], x1 = r4[3], y0 = r4[4], y1 = r4[5];
        mn = fminf(fminf(fminf(m0.x, m0.y), fminf(m0.z, m0.w)),
                   fminf(fminf(m1.x, m1.y), fminf(m1.z, m1.w)));
        mx = fmaxf(fmaxf(fmaxf(x0.x, x0.y), fmaxf(x0.z, x0.w)),
                   fmaxf(fmaxf(x1.x, x1.y), fmaxf(x1.z, x1.w)));
        my = (y0.x + y0.y + y0.z + y0.w + y1.x + y1.y + y1.z + y1.w) * (1.0f / 2048.0f);
    }

    // ---- 2. center in regs, totals; store ONLY boundary xh/yc ------------
    {
        float inv = 1.0f / (mx - mn);
        float t1 = 0.f, t2 = 0.f, vy = 0.f;
#pragma unroll
        for (int s = 0; s < 8; s++) {
            float h = 2.0f * (hr[s] - mn) * inv - 1.0f;
            hr[s] = h;
            float y = xr[s] - my;
            t1 += h; t2 += h * h; vy += y * y;
        }
        if (tid < 52)   { xh[tid] = hr[0];        yc[tid] = xr[0] - my; }
        if (tid >= 204) { xh[1792 + tid] = hr[7]; yc[1792 + tid] = xr[7] - my; }
        for (int o = 16; o; o >>= 1) {
            t1 += __shfl_xor_sync(FULLM, t1, o);
            t2 += __shfl_xor_sync(FULLM, t2, o);
            vy += __shfl_xor_sync(FULLM, vy, o);
        }
        if (lane == 0) { red2[wid] = t1; red2[8 + wid] = t2; red2[16 + wid] = vy; }
        __syncthreads();
    }

    // ---- 3. FFT#1 stage 1 from registers; P/Q prefix scans; totals fold --
    {
        float2 x[8];
#pragma unroll
        for (int s = 0; s < 8; s++) x[s] = make_float2(hr[s], xr[s]);
        radix8_core(x);
        {
            const int pb = zs(tid);
            int ad[8];
#pragma unroll
            for (int s = 0; s < 8; s++) ad[s] = pb ^ zc(256 * s);
            bfly8_store_ad(z, x, ad, twA);
        }

        if (wid == 0) {
            float a0 = 0.f, a1 = 0.f;
            if (lane < 26) { float2 v = ((const float2*)xh)[lane]; a0 = v.x; a1 = v.y; }
            float s1 = a0 + a1, s2 = a0 * a0 + a1 * a1;
            float i1 = s1, i2 = s2;
            for (int o = 1; o < 32; o <<= 1) {
                float u1 = __shfl_up_sync(FULLM, i1, o);
                float u2 = __shfl_up_sync(FULLM, i2, o);
                if (lane >= o) { i1 += u1; i2 += u2; }
            }
            if (lane < 26) {
                float e1 = i1 - s1, e2 = i2 - s2;
                P1[2*lane] = e1;  P1[2*lane+1] = e1 + a0;
                P2[2*lane] = e2;  P2[2*lane+1] = e2 + a0 * a0;
            }
        } else if (wid == 1) {
            float b0 = 0.f, b1 = 0.f;
            if (lane < 26) {
                float2 v = ((const float2*)xh)[1023 - lane];
                b0 = v.y; b1 = v.x;
            }
            float s1 = b0 + b1, s2 = b0 * b0 + b1 * b1;
            float i1 = s1, i2 = s2;
            for (int o = 1; o < 32; o <<= 1) {
                float u1 = __shfl_up_sync(FULLM, i1, o);
                float u2 = __shfl_up_sync(FULLM, i2, o);
                if (lane >= o) { i1 += u1; i2 += u2; }
            }
            if (lane < 26) {
                float e1 = i1 - s1, e2 = i2 - s2;
                Q1[2*lane] = e1;  Q1[2*lane+1] = e1 + b0;
                Q2[2*lane] = e2;  Q2[2*lane+1] = e2 + b0 * b0;
            }
        } else if (wid == 2 && lane < 3) {
            const float* src = red2 + 8 * lane;
            float t = src[0] + src[1] + src[2] + src[3]
                    + src[4] + src[5] + src[6] + src[7];
            if (lane == 0) s_T1 = t;
            else if (lane == 1) s_T2 = t;
            else s_Vy = t;
        }
        __syncthreads();
    }
    stage8_z<32>(z, tid, twB); __syncthreads();
    stage8_z<4>(z, tid, twC);  __syncthreads();
#pragma unroll
    for (int it = 0; it < 2; it++) {
        int pb = zs(4 * (tid + it * 256));
        float2 x[4];
#pragma unroll
        for (int r = 0; r < 4; r++) x[r] = z[pb ^ r];
        radix4_core(x);
#pragma unroll
        for (int r = 0; r < 4; r++) z[pb ^ r] = x[r];
    }
    __syncthreads();

    // ---- 4. untangle: chisq integrands; write P[k] into z lower half -----
    {
        const int zsC[4] = { 0, 17, 1, 16 };
        const int zsW[4] = { 18, 3, 19, 2 };
        const int azS[4] = { 17, 1, 16, 2 };
        const int pz = zs(fpos8(1 + tid));
        const int pw = zs(fpos8(255 - tid));
        const int pk = zs(1 + tid);
        float2 Pk[4];
#pragma unroll
        for (int it = 0; it < 4; it++) {
            int k  = 1 + tid + it * 256;
            int aZ = (tid == 255) ? azS[it] : (pz ^ zsC[it]);
            int aW = pw ^ zsW[it];
            float2 Z = z[aZ];
            float2 W = z[aW];
            const float sc = 0.5f / 2048.0f;
            float h_r = (Z.x + W.x) * sc, h_i = (Z.y - W.y) * sc;
            float s_r = (Z.y + W.y) * sc, s_i = (W.x - Z.x) * sc;
            float pr = h_r * s_r + h_i * s_i;
            float pi = h_i * s_r - h_r * s_i;
            if (k >= 32) {
                float a  = 4.0f * (h_r * h_r + h_i * h_i);
                float cm = 4.0f * sqrtf(pr * pr + pi * pi);
                xv[k - 32]        = a;
                xv[1024 + k - 32] = cm;
            }
            Pk[it] = make_float2(pr, pi);
        }
        __syncthreads();                         // all reads of FFT#1 output done
#pragma unroll
        for (int it = 0; it < 4; it++) {
            if (tid == 255) {
                if (it == 3) s_P1024 = Pk[3];            // P[1024] -> scalar slot
                else         z[257 * (1 + it)] = Pk[it];
            } else {
                z[pk ^ (257 * it)] = Pk[it];
            }
        }
        if (tid == 0) z[0] = make_float2(0.f, 0.f);      // P[0] := 0
        __syncthreads();
    }

    // ---- 5. FFT#2: Hermitian->real via 1024-pt complex FFT ---------------
    {
        const float Hc = 0.70710678118654752f;
        float2 V[4];
        {
            const int pa  = zs(tid);
            const int pb2 = (tid == 0) ? 0 : zs(256 - tid);
            float2 a[4], b[4];
#pragma unroll
            for (int s = 0; s < 4; s++) {
                a[s] = z[pa ^ (257 * s)];
                b[s] = (tid == 0)
                     ? ((s == 0) ? s_P1024 : z[257 * (4 - s)])
                     : z[pb2 ^ (257 * (3 - s))];
            }
#pragma unroll
            for (int s = 0; s < 4; s++) {
                float2 w8s = (s == 0) ? make_float2(1.f, 0.f)
                           : (s == 1) ? make_float2(Hc, -Hc)
                           : (s == 2) ? make_float2(0.f, -1.f)
                                      : make_float2(-Hc, -Hc);
                float2 ca  = make_float2(a[s].x, -a[s].y);
                float2 sum = c_add(ca, b[s]);
                float2 dif = c_sub(ca, b[s]);
                float2 twk = cmul2(twA, w8s);
                float2 idt = cmul2(dif, twk);
                V[s] = make_float2(sum.x - idt.y, sum.y + idt.x);
            }
            // NO barrier: reads were lower half + scalar; writes go UPPER half
            radix4_core(V);
            float2 w1 = cmul2(twA, twA);          // w_1024^tid
            int ad[4];
#pragma unroll
            for (int r = 0; r < 4; r++) ad[r] = 1024 + (pa ^ zc(256 * r));
            bfly4_store_ad(z, V, ad, w1);
            __syncthreads();
        }
        // stage 1: Q=64 — reads UPPER half, writes lower
        {
            int base = (tid >> 6) * 256 + (tid & 63);
            int pb = zs(base);
            int ad[4];
#pragma unroll
            for (int r = 0; r < 4; r++) ad[r] = pb ^ zc(64 * r);
            float2 x[4];
#pragma unroll
            for (int r = 0; r < 4; r++) x[r] = z[1024 + ad[r]];
            radix4_core(x);
            bfly4_store_ad(z, x, ad, twE);
            __syncthreads();
        }
        // stage 2: Q=16
        {
            int base = (tid >> 4) * 64 + (tid & 15);
            int pb = zs(base);
            int ad[4];
#pragma unroll
            for (int r = 0; r < 4; r++) ad[r] = pb ^ zc(16 * r);
            float2 x[4];
#pragma unroll
            for (int r = 0; r < 4; r++) x[r] = z[ad[r]];
            radix4_core(x);
            bfly4_store_ad(z, x, ad, twF);
            __syncthreads();
        }
        // stage 3: Q=4 (j = tid>>6 remap keeps banks conflict-free)
        {
            int base = (tid & 63) * 16 + (tid >> 6);
            int pb = zs(base);
            int ad[4];
#pragma unroll
            for (int r = 0; r < 4; r++) ad[r] = pb ^ zc(4 * r);
            float2 x[4];
#pragma unroll
            for (int r = 0; r < 4; r++) x[r] = z[ad[r]];
            radix4_core(x);
            bfly4_store_ad(z, x, ad, twG);
            __syncthreads();
        }
        // stage 4 (final, untwiddled) pruned to quads feeding needed outputs
        {
            int b = tid;
            int m0 = ((b & 3) << 6) | (((b >> 2) & 3) << 4) | (((b >> 4) & 3) << 2) | (b >> 6);
            if (m0 <= 25 || m0 >= 230) {
                int pb = zs(4 * b);
                float2 x[4];
#pragma unroll
                for (int r = 0; r < 4; r++) x[r] = z[pb ^ r];
                radix4_core(x);
#pragma unroll
                for (int r = 0; r < 4; r++) z[pb ^ r] = x[r];
            }
            __syncthreads();
        }
    }

    // ---- 6. circular->linear corrections, Pearson corr, max -------------
    if (tid < 224) {                      // warps 0..6, 2 threads per shift
        const int pid = tid >> 1;
        const int h   = tid & 1;
        const bool act = (pid < 103);
        float wrap = 0.f, rc = 0.f;
        int d = 0;
        if (act) {
            d = pid - 51;
            int dc = d & 2047;
            int m  = dc >> 1;
            float2 val = z[zs(rev4(m))];
            rc = 2048.0f * ((dc & 1) ? val.y : val.x);
            if (d > 0) {
                for (int t = h; t < d; t += 2) wrap += xh[t] * yc[2048 - d + t];
            } else if (d < 0) {
                int mm = -d;
                for (int t = h; t < mm; t += 2) wrap += xh[2048 - mm + t] * yc[t];
            }
        }
        wrap += __shfl_xor_sync(FULLM, wrap, 1);
        float corr = -2.f;
        if (act) {
            float T1 = s_T1, T2 = s_T2, Vy = s_Vy;
            float acc = rc - wrap;
            float S1, S2v;
            if (d >= 0) { S1 = T1 - P1[d];  S2v = T2 - P2[d]; }
            else        { S1 = T1 - Q1[-d]; S2v = T2 - Q2[-d]; }
            float varx = S2v - S1 * S1 * (1.0f / 2048.0f);
            corr = acc / sqrtf(varx * Vy);
        }
        for (int o = 16; o; o >>= 1)
            corr = fmaxf(corr, __shfl_xor_sync(FULLM, corr, o));
        if (lane == 0) wmax[wid] = corr;
    }

    // ---- 7. dual parallel inclusive scan (packed f32x2) ------------------
    {
        const int i0 = tid * 4;
        float4 a4 = ((const float4*)xv)[tid];
        float4 b4 = ((const float4*)xv)[256 + tid];
        float2 p0 = make_float2(a4.x, b4.x), p1 = make_float2(a4.y, b4.y);
        float2 p2 = make_float2(a4.z, b4.z), p3 = make_float2(a4.w, b4.w);
        if (i0 >= 993)     p0 = make_float2(0.f, 0.f);
        if (i0 + 1 >= 993) p1 = make_float2(0.f, 0.f);
        if (i0 + 2 >= 993) p2 = make_float2(0.f, 0.f);
        if (i0 + 3 >= 993) p3 = make_float2(0.f, 0.f);
        p1 = c_add(p1, p0); p2 = c_add(p2, p1); p3 = c_add(p3, p2);
        float2 last = p3;
        float2 inc  = last;
#pragma unroll
        for (int o = 1; o < 32; o <<= 1) {
            float ux = __shfl_up_sync(FULLM, inc.x, o);
            float uy = __shfl_up_sync(FULLM, inc.y, o);
            if (lane >= o) inc = c_add(inc, make_float2(ux, uy));
        }
        if (lane == 31) wAB[wid] = inc;
        __syncthreads();
        float2 baseE = make_float2(0.f, 0.f);
        for (int w = 0; w < wid; w++) baseE = c_add(baseE, wAB[w]);
        float2 ex = c_add(baseE, c_sub(inc, last));
        float2 q0 = c_add(ex, p0), q1 = c_add(ex, p1);
        float2 q2 = c_add(ex, p2), q3 = c_add(ex, p3);
        if (i0 + 3 < 993) {
            ((float4*)xv)[tid]       = make_float4(q0.x, q1.x, q2.x, q3.x);
            ((float4*)xv)[256 + tid] = make_float4(q0.y, q1.y, q2.y, q3.y);
        } else {
            if (i0 < 993)     { xv[i0]     = q0.x; xv[1024 + i0]     = q0.y; }
            if (i0 + 1 < 993) { xv[i0 + 1] = q1.x; xv[1024 + i0 + 1] = q1.y; }
            if (i0 + 2 < 993) { xv[i0 + 2] = q2.x; xv[1024 + i0 + 2] = q2.y; }
        }
        __syncthreads();
        if (tid == 0) {
            float tot = xv[992];
            s_total   = tot;
            s_inv     = 1.0f / sqrtf(tot);
            s_tot2raw = xv[1024 + 992];
        }
        __syncwarp();      // warp-0-only tail from here on
    }

    // ---- 8. edges: searchsorted(si, k/16*total, 'right'), clip ----------
    if (tid < 17) {
        float v = ((float)tid * (1.0f / 16.0f)) * s_total;
        int lo = 0, hi = 993;
        while (lo < hi) {
            int mid = (lo + hi) >> 1;
            if (xv[mid] <= v) lo = mid + 1; else hi = mid;
        }
        if (lo > 992) lo = 992;
        s_edges[tid] = lo;
    }
    __syncwarp();

    // ---- 9. chisq + final loss ------------------------------------------
    if (tid == 0) {
        float b = wmax[0];
#pragma unroll
        for (int w = 1; w < 7; w++) b = fmaxf(b, wmax[w]);
        float lossbase = (1.0f - b) / (1.0f + b);
        float inv = s_inv;
        float total2 = s_tot2raw * inv;
        float mean = total2 * (1.0f / 16.0f);
        float ssum = 0.f;
        for (int k = 0; k < 16; k++) {
            float r = xv[1024 + s_edges[k + 1]] * inv;
            float l = xv[1024 + s_edges[k]] * inv;
            float d = (r - l) - mean;
            ssum += d * d;
        }
        float chisq = 16.0f * ssum * (1.0f / 15.0f);
        float c3 = chisq * chisq * chisq;
        out[row] = lossbase * powf(1.0f + c3, 1.0f / 6.0f);
    }
}

extern "C" void kernel_launch(void* const* d_in, const int* in_sizes, int n_in,
                              void* d_out, int out_size)
{
    const float* x_hat = (const float*)d_in[0];
    const float* x     = (const float*)d_in[1];
    float* out = (float*)d_out;
    mfl_kernel<<<512, 256>>>(x_hat, x, out);
}

// round 17
// speedup vs baseline: 1.1527x; 1.1118x over previous
#include <cuda_runtime.h>
#include <math.h>
#include <cstring>

// MatchedFilterLoss fused kernel for GB300 (sm_103a)
// Single kernel: 512 blocks x 256 threads. Pearson computed spectrally.
// FFT#1: 2048-pt radix-8 (stage-1 from registers, register twiddles).
// FFT#2: Hermitian->real via half-size 1024-pt complex FFT (radix-4 x5);
//        stage 0 ping-pongs into z's upper half.
// Single merged reduction phase (totals derived by affine algebra).
// Complex add/sub: packed f32x2 PTX ops. Parallel chisq epilogue + __powf.

#define NTH 256
#define FULLM 0xffffffffu

__device__ __forceinline__ int fpos8(int k)
{
    return ((k & 7) << 8) | (((k >> 3) & 7) << 5) | (((k >> 6) & 7) << 2) | (k >> 9);
}

__device__ __forceinline__ int rev4(int m)
{
    return ((m & 3) << 8) | (((m >> 2) & 3) << 6) | (((m >> 4) & 3) << 4)
         | (((m >> 6) & 3) << 2) | (m >> 8);
}

// bank swizzle for float2 array z (XOR-linear); maps [0,1024)->[0,1024)
__device__ __forceinline__ int zs(int p)
{
    return p ^ ((p >> 4) & 15) ^ ((p >> 8) & 7) ^ (((p >> 6) & 1) << 3);
}
__device__ constexpr int zc(int m)
{
    return m ^ ((m >> 4) & 15) ^ ((m >> 8) & 7) ^ (((m >> 6) & 1) << 3);
}

// ---- packed f32x2 complex add/sub --------------------------------------
__device__ __forceinline__ unsigned long long f2u(float2 a)
{
    unsigned long long u; memcpy(&u, &a, 8); return u;
}
__device__ __forceinline__ float2 u2f(unsigned long long u)
{
    float2 a; memcpy(&a, &u, 8); return a;
}
__device__ __forceinline__ float2 c_add(float2 a, float2 b)
{
    unsigned long long r;
    asm("add.rn.f32x2 %0, %1, %2;" : "=l"(r) : "l"(f2u(a)), "l"(f2u(b)));
    return u2f(r);
}
__device__ __forceinline__ float2 c_sub(float2 a, float2 b)
{
    unsigned long long r;
    asm("sub.rn.f32x2 %0, %1, %2;" : "=l"(r) : "l"(f2u(a)), "l"(f2u(b)));
    return u2f(r);
}

__device__ __forceinline__ float2 cmul2(float2 a, float2 w)
{
    return make_float2(a.x*w.x - a.y*w.y, a.x*w.y + a.y*w.x);
}

// w_2048^e = exp(-i*pi*e/1024)
__device__ __forceinline__ float2 tw2048(int e)
{
    float2 w;
    sincospif(-(float)e * (1.0f / 1024.0f), &w.y, &w.x);
    return w;
}

// radix-8 DIF butterfly
__device__ __forceinline__ void radix8_core(float2* x)
{
    const float H = 0.70710678118654752f;
    float2 a0=c_add(x[0],x[4]), d0=c_sub(x[0],x[4]);
    float2 a1=c_add(x[1],x[5]), d1=c_sub(x[1],x[5]);
    float2 a2=c_add(x[2],x[6]), d2=c_sub(x[2],x[6]);
    float2 a3=c_add(x[3],x[7]), d3=c_sub(x[3],x[7]);
    float2 b0=d0;
    float2 b1=make_float2(H*(d1.x+d1.y), H*(d1.y-d1.x));
    float2 b2=make_float2(d2.y, -d2.x);
    float2 b3=make_float2(H*(d3.y-d3.x), -H*(d3.x+d3.y));
    float2 t0=c_add(a0,a2), t1=c_add(a1,a3), t2=c_sub(a0,a2);
    float2 u =c_sub(a1,a3); float2 t3=make_float2(u.y,-u.x);
    x[0]=c_add(t0,t1); x[2]=c_add(t2,t3); x[4]=c_sub(t0,t1); x[6]=c_sub(t2,t3);
    t0=c_add(b0,b2); t1=c_add(b1,b3); t2=c_sub(b0,b2);
    u=c_sub(b1,b3); t3=make_float2(u.y,-u.x);
    x[1]=c_add(t0,t1); x[3]=c_add(t2,t3); x[5]=c_sub(t0,t1); x[7]=c_sub(t2,t3);
}

__device__ __forceinline__ void bfly8_store_ad(float2* z, const float2* x, const int* ad, float2 w1)
{
    float2 w2 = cmul2(w1, w1);
    float2 w3 = cmul2(w2, w1);
    float2 w4 = cmul2(w2, w2);
    float2 w5 = cmul2(w2, w3);
    float2 w6 = cmul2(w3, w3);
    float2 w7 = cmul2(w3, w4);
    z[ad[0]] = x[0];
    z[ad[1]] = cmul2(x[1], w1);
    z[ad[2]] = cmul2(x[2], w2);
    z[ad[3]] = cmul2(x[3], w3);
    z[ad[4]] = cmul2(x[4], w4);
    z[ad[5]] = cmul2(x[5], w5);
    z[ad[6]] = cmul2(x[6], w6);
    z[ad[7]] = cmul2(x[7], w7);
}

template<int Q>
__device__ __forceinline__ void stage8_z(float2* z, int tid, float2 w1)
{
    const int j    = tid & (Q - 1);
    const int base = (tid / Q) * (Q * 8) + j;
    const int pb   = zs(base);
    int ad[8];
#pragma unroll
    for (int s = 0; s < 8; s++) ad[s] = pb ^ zc(Q * s);
    float2 x[8];
#pragma unroll
    for (int s = 0; s < 8; s++) x[s] = z[ad[s]];
    radix8_core(x);
    bfly8_store_ad(z, x, ad, w1);
}

__device__ __forceinline__ void radix4_core(float2* x)
{
    float2 t0=c_add(x[0],x[2]), t1=c_add(x[1],x[3]), t2=c_sub(x[0],x[2]);
    float2 u =c_sub(x[1],x[3]); float2 t3=make_float2(u.y,-u.x);
    x[0]=c_add(t0,t1); x[1]=c_add(t2,t3); x[2]=c_sub(t0,t1); x[3]=c_sub(t2,t3);
}

__device__ __forceinline__ void bfly4_store_ad(float2* z, const float2* x, const int* ad, float2 w1)
{
    float2 w2 = cmul2(w1, w1), w3 = cmul2(w2, w1);
    z[ad[0]] = x[0];
    z[ad[1]] = cmul2(x[1], w1);
    z[ad[2]] = cmul2(x[2], w2);
    z[ad[3]] = cmul2(x[3], w3);
}

__global__ __launch_bounds__(256, 4)
void mfl_kernel(const float* __restrict__ xhat_g,
                const float* __restrict__ x_g,
                float* __restrict__ out)
{
    __shared__ __align__(16) float xh[2048];   // centered x_hat (boundaries only)
    __shared__ __align__(16) float yc[2048];   // centered x (boundaries only)
    __shared__ __align__(16) float xv[2048];   // integrands a|cm, then cumsums
    __shared__ float2 z[2048];                 // FFT workspace (bank-swizzled)
    __shared__ float P1[52], P2[52], Q1[52], Q2[52];
    __shared__ __align__(16) float red1[24];   // mn | mx | sum(x)
    __shared__ __align__(16) float red2[24];   // sum(xh) | sum(xh^2) | sum(x^2)
    __shared__ float2 wAB[8];
    __shared__ float wmax[7];
    __shared__ float2 s_P1024;                 // relocated P[1024] (Nyquist)
    __shared__ float s_T1, s_T2, s_Vy;
    __shared__ float s_total, s_tot2raw, s_inv;
    __shared__ int   s_edges[17];

    const int tid  = threadIdx.x;
    const int lane = tid & 31;
    const int wid  = tid >> 5;
    const int row  = blockIdx.x;

    const float* xh_in = xhat_g + (size_t)row * 2048;
    const float* x_in  = x_g    + (size_t)row * 2048;

    // per-thread twiddles: 3 sincospif + 3 derived/constant
    float2 twA = tw2048(tid);               // 2048 FFT Q=256 stage + twist base
    float2 twE = tw2048(8 * (tid & 63));    // 1024 FFT stage1 (Q=64)
    float2 twF = tw2048(32 * (tid & 15));   // 1024 FFT stage2 (Q=16)
    float2 twB = (tid & 32)
        ? cmul2(twE, make_float2(0.70710678118654752f, 0.70710678118654752f))
        : twE;
    int cc = tid & 3;
    float2 twC = (cc == 0) ? make_float2(1.f, 0.f)
               : (cc == 1) ? make_float2(0.98078528040323044f, -0.19509032201612827f)
               : (cc == 2) ? make_float2(0.92387953251128676f, -0.38268343236508977f)
                           : make_float2(0.83146961230254524f, -0.55557023301960222f);
    int gg = tid >> 6;
    float2 twG = (gg == 0) ? make_float2(1.f, 0.f)
               : (gg == 1) ? make_float2(0.92387953251128676f, -0.38268343236508977f)
               : (gg == 2) ? make_float2(0.70710678118654752f, -0.70710678118654752f)
                           : make_float2(0.38268343236508977f, -0.92387953251128676f);

    // ---- 1. load + SINGLE merged reduction (6 quantities) ----------------
    float hr[8], xr[8];
#pragma unroll
    for (int s = 0; s < 8; s++) {
        hr[s] = xh_in[tid + 256 * s];
        xr[s] = x_in[tid + 256 * s];
    }
    float mn, mx, my;
    {
        float pmn = 1e30f, pmx = -1e30f, psy = 0.f;
        float ps1 = 0.f, ps2 = 0.f, pq2 = 0.f;
#pragma unroll
        for (int s = 0; s < 8; s++) {
            float h = hr[s], y = xr[s];
            pmn = fminf(pmn, h); pmx = fmaxf(pmx, h);
            psy += y; pq2 += y * y;
            ps1 += h; ps2 += h * h;
        }
        for (int o = 16; o; o >>= 1) {
            pmn = fminf(pmn, __shfl_xor_sync(FULLM, pmn, o));
            pmx = fmaxf(pmx, __shfl_xor_sync(FULLM, pmx, o));
            psy += __shfl_xor_sync(FULLM, psy, o);
            ps1 += __shfl_xor_sync(FULLM, ps1, o);
            ps2 += __shfl_xor_sync(FULLM, ps2, o);
            pq2 += __shfl_xor_sync(FULLM, pq2, o);
        }
        if (lane == 0) {
            red1[wid] = pmn; red1[8 + wid] = pmx; red1[16 + wid] = psy;
            red2[wid] = ps1; red2[8 + wid] = ps2; red2[16 + wid] = pq2;
        }
        __syncthreads();
        const float4* r4 = (const float4*)red1;
        float4 m0 = r4[0], m1 = r4[1], x0 = r4[2], x1 = r4[3], y0 = r4[4], y1 = r4[5];
        mn = fminf(fminf(fminf(m0.x, m0.y), fminf(m0.z, m0.w)),
                   fminf(fminf(m1.x, m1.y), fminf(m1.z, m1.w)));
        mx = fmaxf(fmaxf(fmaxf(x0.x, x0.y), fmaxf(x0.z, x0.w)),
                   fmaxf(fmaxf(x1.x, x1.y), fmaxf(x1.z, x1.w)));
        my = (y0.x + y0.y + y0.z + y0.w + y1.x + y1.y + y1.z + y1.w) * (1.0f / 2048.0f);
    }

    // ---- 2. center in regs; boundary xh/yc stores (no reduction) ---------
    {
        float inv = 1.0f / (mx - mn);
#pragma unroll
        for (int s = 0; s < 8; s++)
            hr[s] = 2.0f * (hr[s] - mn) * inv - 1.0f;
        if (tid < 52)   { xh[tid] = hr[0];        yc[tid] = xr[0] - my; }
        if (tid >= 204) { xh[1792 + tid] = hr[7]; yc[1792 + tid] = xr[7] - my; }
        __syncthreads();
    }

    // ---- 3. FFT#1 stage 1 from registers; P/Q prefix scans; totals -------
    {
        float2 x[8];
#pragma unroll
        for (int s = 0; s < 8; s++) x[s] = make_float2(hr[s], xr[s]);
        radix8_core(x);
        {
            const int pb = zs(tid);
            int ad[8];
#pragma unroll
            for (int s = 0; s < 8; s++) ad[s] = pb ^ zc(256 * s);
            bfly8_store_ad(z, x, ad, twA);
        }

        if (wid == 0) {
            float a0 = 0.f, a1 = 0.f;
            if (lane < 26) { float2 v = ((const float2*)xh)[lane]; a0 = v.x; a1 = v.y; }
            float s1 = a0 + a1, s2 = a0 * a0 + a1 * a1;
            float i1 = s1, i2 = s2;
            for (int o = 1; o < 32; o <<= 1) {
                float u1 = __shfl_up_sync(FULLM, i1, o);
                float u2 = __shfl_up_sync(FULLM, i2, o);
                if (lane >= o) { i1 += u1; i2 += u2; }
            }
            if (lane < 26) {
                float e1 = i1 - s1, e2 = i2 - s2;
                P1[2*lane] = e1;  P1[2*lane+1] = e1 + a0;
                P2[2*lane] = e2;  P2[2*lane+1] = e2 + a0 * a0;
            }
        } else if (wid == 1) {
            float b0 = 0.f, b1 = 0.f;
            if (lane < 26) {
                float2 v = ((const float2*)xh)[1023 - lane];
                b0 = v.y; b1 = v.x;
            }
            float s1 = b0 + b1, s2 = b0 * b0 + b1 * b1;
            float i1 = s1, i2 = s2;
            for (int o = 1; o < 32; o <<= 1) {
                float u1 = __shfl_up_sync(FULLM, i1, o);
                float u2 = __shfl_up_sync(FULLM, i2, o);
                if (lane >= o) { i1 += u1; i2 += u2; }
            }
            if (lane < 26) {
                float e1 = i1 - s1, e2 = i2 - s2;
                Q1[2*lane] = e1;  Q1[2*lane+1] = e1 + b0;
                Q2[2*lane] = e2;  Q2[2*lane+1] = e2 + b0 * b0;
            }
        } else if (wid == 2 && lane == 0) {
            // affine-derived totals: h = a*x + c
            float S1 = red2[0] + red2[1] + red2[2] + red2[3]
                     + red2[4] + red2[5] + red2[6] + red2[7];
            float S2 = red2[8] + red2[9] + red2[10] + red2[11]
                     + red2[12] + red2[13] + red2[14] + red2[15];
            float Qq = red2[16] + red2[17] + red2[18] + red2[19]
                     + red2[20] + red2[21] + red2[22] + red2[23];
            float invr = 1.0f / (mx - mn);
            float a = 2.0f * invr;
            float c = -2.0f * mn * invr - 1.0f;
            s_T1 = a * S1 + 2048.0f * c;
            s_T2 = a * a * S2 + 2.0f * a * c * S1 + 2048.0f * c * c;
            s_Vy = Qq - 2048.0f * my * my;
        }
        __syncthreads();
    }
    stage8_z<32>(z, tid, twB); __syncthreads();
    stage8_z<4>(z, tid, twC);  __syncthreads();
#pragma unroll
    for (int it = 0; it < 2; it++) {
        int pb = zs(4 * (tid + it * 256));
        float2 x[4];
#pragma unroll
        for (int r = 0; r < 4; r++) x[r] = z[pb ^ r];
        radix4_core(x);
#pragma unroll
        for (int r = 0; r < 4; r++) z[pb ^ r] = x[r];
    }
    __syncthreads();

    // ---- 4. untangle: chisq integrands; write P[k] into z lower half -----
    {
        const int zsC[4] = { 0, 17, 1, 16 };
        const int zsW[4] = { 18, 3, 19, 2 };
        const int azS[4] = { 17, 1, 16, 2 };
        const int pz = zs(fpos8(1 + tid));
        const int pw = zs(fpos8(255 - tid));
        const int pk = zs(1 + tid);
        float2 Pk[4];
#pragma unroll
        for (int it = 0; it < 4; it++) {
            int k  = 1 + tid + it * 256;
            int aZ = (tid == 255) ? azS[it] : (pz ^ zsC[it]);
            int aW = pw ^ zsW[it];
            float2 Z = z[aZ];
            float2 W = z[aW];
            const float sc = 0.5f / 2048.0f;
            float h_r = (Z.x + W.x) * sc, h_i = (Z.y - W.y) * sc;
            float s_r = (Z.y + W.y) * sc, s_i = (W.x - Z.x) * sc;
            float pr = h_r * s_r + h_i * s_i;
            float pi = h_i * s_r - h_r * s_i;
            if (k >= 32) {
                float a  = 4.0f * (h_r * h_r + h_i * h_i);
                float cm = 4.0f * sqrtf(pr * pr + pi * pi);
                xv[k - 32]        = a;
                xv[1024 + k - 32] = cm;
            }
            Pk[it] = make_float2(pr, pi);
        }
        __syncthreads();                         // all reads of FFT#1 output done
#pragma unroll
        for (int it = 0; it < 4; it++) {
            if (tid == 255) {
                if (it == 3) s_P1024 = Pk[3];
                else         z[257 * (1 + it)] = Pk[it];
            } else {
                z[pk ^ (257 * it)] = Pk[it];
            }
        }
        if (tid == 0) z[0] = make_float2(0.f, 0.f);
        __syncthreads();
    }

    // ---- 5. FFT#2: Hermitian->real via 1024-pt complex FFT ---------------
    {
        const float Hc = 0.70710678118654752f;
        float2 V[4];
        {
            const int pa  = zs(tid);
            const int pb2 = (tid == 0) ? 0 : zs(256 - tid);
            float2 a[4], b[4];
#pragma unroll
            for (int s = 0; s < 4; s++) {
                a[s] = z[pa ^ (257 * s)];
                b[s] = (tid == 0)
                     ? ((s == 0) ? s_P1024 : z[257 * (4 - s)])
                     : z[pb2 ^ (257 * (3 - s))];
            }
#pragma unroll
            for (int s = 0; s < 4; s++) {
                float2 w8s = (s == 0) ? make_float2(1.f, 0.f)
                           : (s == 1) ? make_float2(Hc, -Hc)
                           : (s == 2) ? make_float2(0.f, -1.f)
                                      : make_float2(-Hc, -Hc);
                float2 ca  = make_float2(a[s].x, -a[s].y);
                float2 sum = c_add(ca, b[s]);
                float2 dif = c_sub(ca, b[s]);
                float2 twk = cmul2(twA, w8s);
                float2 idt = cmul2(dif, twk);
                V[s] = make_float2(sum.x - idt.y, sum.y + idt.x);
            }
            radix4_core(V);
            float2 w1 = cmul2(twA, twA);
            int ad[4];
#pragma unroll
            for (int r = 0; r < 4; r++) ad[r] = 1024 + (pa ^ zc(256 * r));
            bfly4_store_ad(z, V, ad, w1);
            __syncthreads();
        }
        // stage 1: Q=64 — reads UPPER half, writes lower
        {
            int base = (tid >> 6) * 256 + (tid & 63);
            int pb = zs(base);
            int ad[4];
#pragma unroll
            for (int r = 0; r < 4; r++) ad[r] = pb ^ zc(64 * r);
            float2 x[4];
#pragma unroll
            for (int r = 0; r < 4; r++) x[r] = z[1024 + ad[r]];
            radix4_core(x);
            bfly4_store_ad(z, x, ad, twE);
            __syncthreads();
        }
        // stage 2: Q=16
        {
            int base = (tid >> 4) * 64 + (tid & 15);
            int pb = zs(base);
            int ad[4];
#pragma unroll
            for (int r = 0; r < 4; r++) ad[r] = pb ^ zc(16 * r);
            float2 x[4];
#pragma unroll
            for (int r = 0; r < 4; r++) x[r] = z[ad[r]];
            radix4_core(x);
            bfly4_store_ad(z, x, ad, twF);
            __syncthreads();
        }
        // stage 3: Q=4 (j = tid>>6 remap keeps banks conflict-free)
        {
            int base = (tid & 63) * 16 + (tid >> 6);
            int pb = zs(base);
            int ad[4];
#pragma unroll
            for (int r = 0; r < 4; r++) ad[r] = pb ^ zc(4 * r);
            float2 x[4];
#pragma unroll
            for (int r = 0; r < 4; r++) x[r] = z[ad[r]];
            radix4_core(x);
            bfly4_store_ad(z, x, ad, twG);
            __syncthreads();
        }
        // stage 4 (final, untwiddled) pruned to quads feeding needed outputs
        {
            int b = tid;
            int m0 = ((b & 3) << 6) | (((b >> 2) & 3) << 4) | (((b >> 4) & 3) << 2) | (b >> 6);
            if (m0 <= 25 || m0 >= 230) {
                int pb = zs(4 * b);
                float2 x[4];
#pragma unroll
                for (int r = 0; r < 4; r++) x[r] = z[pb ^ r];
                radix4_core(x);
#pragma unroll
                for (int r = 0; r < 4; r++) z[pb ^ r] = x[r];
            }
            __syncthreads();
        }
    }

    // ---- 6. circular->linear corrections, Pearson corr, max -------------
    if (tid < 224) {                      // warps 0..6, 2 threads per shift
        const int pid = tid >> 1;
        const int h   = tid & 1;
        const bool act = (pid < 103);
        float wrap = 0.f, rc = 0.f;
        int d = 0;
        if (act) {
            d = pid - 51;
            int dc = d & 2047;
            int m  = dc >> 1;
            float2 val = z[zs(rev4(m))];
            rc = 2048.0f * ((dc & 1) ? val.y : val.x);
            if (d > 0) {
                for (int t = h; t < d; t += 2) wrap += xh[t] * yc[2048 - d + t];
            } else if (d < 0) {
                int mm = -d;
                for (int t = h; t < mm; t += 2) wrap += xh[2048 - mm + t] * yc[t];
            }
        }
        wrap += __shfl_xor_sync(FULLM, wrap, 1);
        float corr = -2.f;
        if (act) {
            float T1 = s_T1, T2 = s_T2, Vy = s_Vy;
            float acc = rc - wrap;
            float S1, S2v;
            if (d >= 0) { S1 = T1 - P1[d];  S2v = T2 - P2[d]; }
            else        { S1 = T1 - Q1[-d]; S2v = T2 - Q2[-d]; }
            float varx = S2v - S1 * S1 * (1.0f / 2048.0f);
            corr = acc / sqrtf(varx * Vy);
        }
        for (int o = 16; o; o >>= 1)
            corr = fmaxf(corr, __shfl_xor_sync(FULLM, corr, o));
        if (lane == 0) wmax[wid] = corr;
    }

    // ---- 7. dual parallel inclusive scan (packed f32x2) ------------------
    {
        const int i0 = tid * 4;
        float4 a4 = ((const float4*)xv)[tid];
        float4 b4 = ((const float4*)xv)[256 + tid];
        float2 p0 = make_float2(a4.x, b4.x), p1 = make_float2(a4.y, b4.y);
        float2 p2 = make_float2(a4.z, b4.z), p3 = make_float2(a4.w, b4.w);
        if (i0 >= 993)     p0 = make_float2(0.f, 0.f);
        if (i0 + 1 >= 993) p1 = make_float2(0.f, 0.f);
        if (i0 + 2 >= 993) p2 = make_float2(0.f, 0.f);
        if (i0 + 3 >= 993) p3 = make_float2(0.f, 0.f);
        p1 = c_add(p1, p0); p2 = c_add(p2, p1); p3 = c_add(p3, p2);
        float2 last = p3;
        float2 inc  = last;
#pragma unroll
        for (int o = 1; o < 32; o <<= 1) {
            float ux = __shfl_up_sync(FULLM, inc.x, o);
            float uy = __shfl_up_sync(FULLM, inc.y, o);
            if (lane >= o) inc = c_add(inc, make_float2(ux, uy));
        }
        if (lane == 31) wAB[wid] = inc;
        __syncthreads();
        float2 baseE = make_float2(0.f, 0.f);
        for (int w = 0; w < wid; w++) baseE = c_add(baseE, wAB[w]);
        float2 ex = c_add(baseE, c_sub(inc, last));
        float2 q0 = c_add(ex, p0), q1 = c_add(ex, p1);
        float2 q2 = c_add(ex, p2), q3 = c_add(ex, p3);
        if (i0 + 3 < 993) {
            ((float4*)xv)[tid]       = make_float4(q0.x, q1.x, q2.x, q3.x);
            ((float4*)xv)[256 + tid] = make_float4(q0.y, q1.y, q2.y, q3.y);
        } else {
            if (i0 < 993)     { xv[i0]     = q0.x; xv[1024 + i0]     = q0.y; }
            if (i0 + 1 < 993) { xv[i0 + 1] = q1.x; xv[1024 + i0 + 1] = q1.y; }
            if (i0 + 2 < 993) { xv[i0 + 2] = q2.x; xv[1024 + i0 + 2] = q2.y; }
        }
        __syncthreads();
        if (tid == 0) {
            float tot = xv[992];
            s_total   = tot;
            s_inv     = 1.0f / sqrtf(tot);
            s_tot2raw = xv[1024 + 992];
        }
        __syncwarp();      // warp-0-only tail from here on
    }

    // ---- 8. edges: searchsorted(si, k/16*total, 'right'), clip ----------
    if (tid < 17) {
        float v = ((float)tid * (1.0f / 16.0f)) * s_total;
        int lo = 0, hi = 993;
        while (lo < hi) {
            int mid = (lo + hi) >> 1;
            if (xv[mid] <= v) lo = mid + 1; else hi = mid;
        }
        if (lo > 992) lo = 992;
        s_edges[tid] = lo;
    }
    __syncwarp();

    // ---- 9. chisq (16 parallel lanes) + final loss -----------------------
    if (tid < 16) {
        float inv = s_inv;
        float total2 = s_tot2raw * inv;
        float mean = total2 * (1.0f / 16.0f);
        float r = xv[1024 + s_edges[tid + 1]];
        float l = xv[1024 + s_edges[tid]];
        float dd = (r - l) * inv - mean;
        float v = dd * dd;
#pragma unroll
        for (int o = 8; o; o >>= 1)
            v += __shfl_xor_sync(0x0000ffffu, v, o);
        if (tid == 0) {
            float b = wmax[0];
#pragma unroll
            for (int w = 1; w < 7; w++) b = fmaxf(b, wmax[w]);
            float lossbase = (1.0f - b) / (1.0f + b);
            float chisq = 16.0f * v * (1.0f / 15.0f);
            float c3 = chisq * chisq * chisq;
            out[row] = lossbase * __powf(1.0f + c3, 1.0f / 6.0f);
        }
    }
}

extern "C" void kernel_launch(void* const* d_in, const int* in_sizes, int n_in,
                              void* d_out, int out_size)
{
    const float* x_hat = (const float*)d_in[0];
    const float* x     = (const float*)d_in[1];
    float* out = (float*)d_out;
    mfl_kernel<<<512, 256>>>(x_hat, x, out);
}